// round 1
// baseline (speedup 1.0000x reference)
#include <cuda_runtime.h>
#include <math.h>
#include <float.h>
#include <stdint.h>

#define BB   8
#define NN   2048
#define DDIM 256
#define KNB  8
#define NEDGE (BB*NN*KNB)     // 131072
#define BN_EPS 1e-5f

// ---------------- scratch (static device globals; no allocation) ----------------
__device__ float g_x[BB*NN*DDIM];          // merged point features  [B*N, D]
__device__ float g_sq[BB*NN];              // |x|^2 per point
__device__ float g_dist[BB*NN*NN];         // distance matrix (128 MB)
__device__ int   g_nidx[BB*NN*KNB];        // knn indices
__device__ float g_h1[NEDGE*DDIM];         // edge layer1 relu output (128 MB)
__device__ float g_h2[NEDGE*DDIM];         // edge layer2 relu output (128 MB)
__device__ float g_stats[4*DDIM];          // [sum1, sqsum1, sum2, sqsum2]
__device__ float g_mv[4*DDIM];             // [scale1, shift1, scale2, shift2]
__device__ float g_pmax[BB*64*DDIM];       // partial max

// ---------------- helpers ----------------
__device__ __forceinline__ unsigned long long pack2(float lo, float hi) {
    unsigned long long r;
    asm("mov.b64 %0, {%1, %2};" : "=l"(r) : "f"(lo), "f"(hi));
    return r;
}
__device__ __forceinline__ void unpack2(unsigned long long v, float& lo, float& hi) {
    asm("mov.b64 {%0, %1}, %2;" : "=f"(lo), "=f"(hi) : "l"(v));
}
// d = a*b + d on packed f32x2 (Blackwell FFMA2 path; 2x fp32 throughput)
__device__ __forceinline__ void ffma2(unsigned long long& d, unsigned long long a, unsigned long long b) {
    asm("fma.rn.f32x2 %0, %1, %2, %0;" : "+l"(d) : "l"(a), "l"(b));
}
__device__ __forceinline__ float wredsum(float s) {
#pragma unroll
    for (int o = 16; o; o >>= 1) s += __shfl_xor_sync(0xffffffffu, s, o);
    return s;
}

// ---------------- K1: point features + merge GEMM ----------------
// 16 points per block, 256 threads. Phase A: each warp builds 2 points' 768-dim
// concat feature (ce | col | pos, each l2-normalized) in shared. Phase B: thread d
// computes x[p][d] for all 16 points via f32x2 GEMM. Also writes |x|^2.
__global__ void __launch_bounds__(256) k1_features(
    const int*   __restrict__ class_idx, const float* __restrict__ colors,
    const float* __restrict__ positions, const float* __restrict__ class_table,
    const float* __restrict__ posW1, const float* __restrict__ posb1,
    const float* __restrict__ posW2, const float* __restrict__ posb2,
    const float* __restrict__ colW1, const float* __restrict__ colb1,
    const float* __restrict__ colW2, const float* __restrict__ colb2,
    const float* __restrict__ mW,    const float* __restrict__ mb)
{
    __shared__ __align__(16) float fs[768*16];   // [c][p], 48KB
    int tid = threadIdx.x, lane = tid & 31, w = tid >> 5;
    int g0 = blockIdx.x * 16;

    // zero BN-stat accumulators once per launch (K1 fully precedes K3 in stream order)
    if (blockIdx.x == 0)
        for (int i = tid; i < 4*DDIM; i += 256) g_stats[i] = 0.f;

    for (int pp = 0; pp < 2; pp++) {
        int p = w*2 + pp;
        int g = g0 + p;
        // --- class embedding, l2norm ---
        int cls = class_idx[g];
        float v[8]; float s = 0.f;
#pragma unroll
        for (int t = 0; t < 8; t++) { v[t] = class_table[cls*DDIM + lane + 32*t]; s += v[t]*v[t]; }
        s = wredsum(s);
        float sc = 1.f / fmaxf(sqrtf(s), 1e-12f);
#pragma unroll
        for (int t = 0; t < 8; t++) fs[(lane + 32*t)*16 + p] = v[t]*sc;

        // --- color MLP 3->32->256, relu, l2norm ---
        float a0 = colors[g*3+0], a1 = colors[g*3+1], a2 = colors[g*3+2];
        float h = fmaxf(colb1[lane] + a0*colW1[lane] + a1*colW1[32+lane] + a2*colW1[64+lane], 0.f);
#pragma unroll
        for (int t = 0; t < 8; t++) v[t] = colb2[lane + 32*t];
#pragma unroll 8
        for (int k = 0; k < 32; k++) {
            float hk = __shfl_sync(0xffffffffu, h, k);
#pragma unroll
            for (int t = 0; t < 8; t++) v[t] += hk * colW2[k*DDIM + lane + 32*t];
        }
        s = 0.f;
#pragma unroll
        for (int t = 0; t < 8; t++) { v[t] = fmaxf(v[t], 0.f); s += v[t]*v[t]; }
        s = wredsum(s);
        sc = 1.f / fmaxf(sqrtf(s), 1e-12f);
#pragma unroll
        for (int t = 0; t < 8; t++) fs[(256 + lane + 32*t)*16 + p] = v[t]*sc;

        // --- position MLP ---
        a0 = positions[g*3+0]; a1 = positions[g*3+1]; a2 = positions[g*3+2];
        h = fmaxf(posb1[lane] + a0*posW1[lane] + a1*posW1[32+lane] + a2*posW1[64+lane], 0.f);
#pragma unroll
        for (int t = 0; t < 8; t++) v[t] = posb2[lane + 32*t];
#pragma unroll 8
        for (int k = 0; k < 32; k++) {
            float hk = __shfl_sync(0xffffffffu, h, k);
#pragma unroll
            for (int t = 0; t < 8; t++) v[t] += hk * posW2[k*DDIM + lane + 32*t];
        }
        s = 0.f;
#pragma unroll
        for (int t = 0; t < 8; t++) { v[t] = fmaxf(v[t], 0.f); s += v[t]*v[t]; }
        s = wredsum(s);
        sc = 1.f / fmaxf(sqrtf(s), 1e-12f);
#pragma unroll
        for (int t = 0; t < 8; t++) fs[(512 + lane + 32*t)*16 + p] = v[t]*sc;
    }
    __syncthreads();

    // Phase B: merge GEMM [16 x 768] @ [768 x 256] per block
    int d = tid;
    float bv = mb[d];
    unsigned long long acc[8];
    unsigned long long bi = pack2(bv, bv);
#pragma unroll
    for (int q = 0; q < 8; q++) acc[q] = bi;
    for (int c = 0; c < 768; c++) {
        float wv = mW[c*DDIM + d];
        unsigned long long w2 = pack2(wv, wv);
        const ulonglong2* f2 = (const ulonglong2*)&fs[c*16];
#pragma unroll
        for (int q = 0; q < 4; q++) {
            ulonglong2 u = f2[q];
            ffma2(acc[2*q],   w2, u.x);
            ffma2(acc[2*q+1], w2, u.y);
        }
    }
    __syncthreads();
    if (tid < 16) fs[tid] = 0.f;   // reuse shared as per-point sumsq accumulator
    __syncthreads();
    float xv[16];
#pragma unroll
    for (int q = 0; q < 8; q++) {
        float v0, v1; unpack2(acc[q], v0, v1);
        v0 = fmaxf(v0, 0.f); v1 = fmaxf(v1, 0.f);
        g_x[(g0 + 2*q  )*DDIM + d] = v0;
        g_x[(g0 + 2*q+1)*DDIM + d] = v1;
        xv[2*q] = v0*v0; xv[2*q+1] = v1*v1;
    }
#pragma unroll
    for (int p = 0; p < 16; p++) {
        float s = wredsum(xv[p]);
        if (lane == 0) atomicAdd(&fs[p], s);
    }
    __syncthreads();
    if (tid < 16) g_sq[g0 + tid] = fs[tid];
}

// ---------------- K2a: distance matrix (gram GEMM, 64x64 tiles) ----------------
__global__ void __launch_bounds__(256) k2_dist()
{
    __shared__ __align__(16) float As[16][64];
    __shared__ __align__(16) float Bs[16][64];
    int b = blockIdx.z;
    int i0 = blockIdx.y * 64, j0 = blockIdx.x * 64;
    int tid = threadIdx.x;
    int tx = tid & 15, ty = tid >> 4;
    const float* xb = g_x + b*NN*DDIM;
    int lrow = tid >> 2, lk = (tid & 3) * 4;
    unsigned long long acc[4][2];
#pragma unroll
    for (int i = 0; i < 4; i++) { acc[i][0] = 0ULL; acc[i][1] = 0ULL; }

    for (int kc = 0; kc < DDIM; kc += 16) {
        float4 av = *(const float4*)&xb[(i0 + lrow)*DDIM + kc + lk];
        float4 bv = *(const float4*)&xb[(j0 + lrow)*DDIM + kc + lk];
        As[lk+0][lrow] = av.x; As[lk+1][lrow] = av.y; As[lk+2][lrow] = av.z; As[lk+3][lrow] = av.w;
        Bs[lk+0][lrow] = bv.x; Bs[lk+1][lrow] = bv.y; Bs[lk+2][lrow] = bv.z; Bs[lk+3][lrow] = bv.w;
        __syncthreads();
#pragma unroll
        for (int k = 0; k < 16; k++) {
            float4 a = *(const float4*)&As[k][ty*4];
            ulonglong2 bp = *(const ulonglong2*)&Bs[k][tx*4];
            unsigned long long a0 = pack2(a.x, a.x), a1 = pack2(a.y, a.y);
            unsigned long long a2 = pack2(a.z, a.z), a3 = pack2(a.w, a.w);
            ffma2(acc[0][0], a0, bp.x); ffma2(acc[0][1], a0, bp.y);
            ffma2(acc[1][0], a1, bp.x); ffma2(acc[1][1], a1, bp.y);
            ffma2(acc[2][0], a2, bp.x); ffma2(acc[2][1], a2, bp.y);
            ffma2(acc[3][0], a3, bp.x); ffma2(acc[3][1], a3, bp.y);
        }
        __syncthreads();
    }
    float sqj[4];
#pragma unroll
    for (int jj = 0; jj < 4; jj++) sqj[jj] = g_sq[b*NN + j0 + tx*4 + jj];
#pragma unroll
    for (int ii = 0; ii < 4; ii++) {
        int i = i0 + ty*4 + ii;
        float sqi = g_sq[b*NN + i];
        float d0, d1, d2, d3;
        unpack2(acc[ii][0], d0, d1);
        unpack2(acc[ii][1], d2, d3);
        float4 o;
        o.x = sqi + sqj[0] - 2.f*d0;
        o.y = sqi + sqj[1] - 2.f*d1;
        o.z = sqi + sqj[2] - 2.f*d2;
        o.w = sqi + sqj[3] - 2.f*d3;
        *(float4*)&g_dist[(b*NN + i)*NN + j0 + tx*4] = o;
    }
}

// ---------------- K2b: top-8 smallest per row (warp per row) ----------------
// Lexicographic (d, idx) ordering matches jax.lax.top_k tie-breaking (lower idx first).
__global__ void __launch_bounds__(256) k2b_topk()
{
    int lane = threadIdx.x & 31;
    int wr = threadIdx.x >> 5;
    int row = blockIdx.x * 8 + wr;          // 0..B*N-1
    const float* dr = g_dist + (size_t)row * NN;
    float dv[8]; int di[8];
#pragma unroll
    for (int t = 0; t < 8; t++) { dv[t] = FLT_MAX; di[t] = 0x7fffffff; }
    for (int j = lane; j < NN; j += 32) {
        float cd = dr[j]; int ci = j;
#pragma unroll
        for (int t = 0; t < 8; t++) {
            bool lt = (cd < dv[t]) || (cd == dv[t] && ci < di[t]);
            if (lt) { float td = dv[t]; dv[t] = cd; cd = td;
                      int   ti = di[t]; di[t] = ci; ci = ti; }
        }
    }
    // merge across warp: 8 extraction rounds
    for (int r = 0; r < 8; r++) {
        float bd = dv[0]; int bi2 = di[0];
#pragma unroll
        for (int o = 16; o; o >>= 1) {
            float od = __shfl_xor_sync(0xffffffffu, bd, o);
            int   oi = __shfl_xor_sync(0xffffffffu, bi2, o);
            if (od < bd || (od == bd && oi < bi2)) { bd = od; bi2 = oi; }
        }
        if (dv[0] == bd && di[0] == bi2) {   // winner lane pops (idx unique per lane)
#pragma unroll
            for (int t = 0; t < 7; t++) { dv[t] = dv[t+1]; di[t] = di[t+1]; }
            dv[7] = FLT_MAX; di[7] = 0x7fffffff;
        }
        if (lane == 0) g_nidx[row*KNB + r] = bi2;
    }
}

// ---------------- K3: edge gather + GEMM1 (2D->D) + relu + BN1 stats ----------------
// 4 nodes = 32 edges per block; es is [512][36] (stride 36 keeps 16B alignment, 4-way bank).
__global__ void __launch_bounds__(256) k3_edge1(const float* __restrict__ W1, const float* __restrict__ b1)
{
    extern __shared__ __align__(16) float es[];
    int tid = threadIdx.x, lane = tid & 31, w = tid >> 5;
    int node0 = blockIdx.x * 4;
#pragma unroll
    for (int ee = 0; ee < 4; ee++) {
        int e = w*4 + ee;
        int q = e >> 3, kk = e & 7;
        int g = node0 + q;
        int b = g >> 11;                      // g / NN
        int jn = g_nidx[g*KNB + kk];
        const float* xi = g_x + g*DDIM;
        const float* xj = g_x + (b*NN + jn)*DDIM;
#pragma unroll
        for (int t = 0; t < 8; t++) {
            int c = lane + 32*t;
            float a = xi[c], bb = xj[c];
            es[c*36 + e] = a;                 // [xi, xj-xi] concat
            es[(256 + c)*36 + e] = bb - a;
        }
    }
    __syncthreads();
    int d = tid;
    float bias = b1[d];
    unsigned long long acc[16];
    unsigned long long bi = pack2(bias, bias);
#pragma unroll
    for (int q = 0; q < 16; q++) acc[q] = bi;
    for (int c = 0; c < 512; c++) {
        float wv = W1[c*DDIM + d];
        unsigned long long w2 = pack2(wv, wv);
        const ulonglong2* f2 = (const ulonglong2*)&es[c*36];
#pragma unroll
        for (int q = 0; q < 8; q++) {
            ulonglong2 u = f2[q];
            ffma2(acc[2*q],   w2, u.x);
            ffma2(acc[2*q+1], w2, u.y);
        }
    }
    int E0 = blockIdx.x * 32;
    float s = 0.f, s2 = 0.f;
#pragma unroll
    for (int q = 0; q < 16; q++) {
        float v0, v1; unpack2(acc[q], v0, v1);
        v0 = fmaxf(v0, 0.f); v1 = fmaxf(v1, 0.f);
        g_h1[(E0 + 2*q  )*DDIM + d] = v0;
        g_h1[(E0 + 2*q+1)*DDIM + d] = v1;
        s += v0 + v1; s2 += v0*v0 + v1*v1;
    }
    atomicAdd(&g_stats[d], s);
    atomicAdd(&g_stats[DDIM + d], s2);
}

// ---------------- finalize BN stats -> scale/shift ----------------
__global__ void k_finalize(int si, int mo, const float* __restrict__ gamma, const float* __restrict__ beta)
{
    int d = threadIdx.x;
    float inv = 1.f / (float)NEDGE;
    float m = g_stats[si + d] * inv;
    float v = g_stats[si + DDIM + d] * inv - m*m;
    float rstd = rsqrtf(v + BN_EPS);
    float sc = rstd * gamma[d];
    g_mv[mo + d] = sc;
    g_mv[mo + DDIM + d] = beta[d] - m*sc;
}

// ---------------- K4: BN1-apply + GEMM2 (D->D) + relu + BN2 stats ----------------
__global__ void __launch_bounds__(256) k4_edge2(const float* __restrict__ W2, const float* __restrict__ b2)
{
    __shared__ __align__(16) float es[256*36];
    int tid = threadIdx.x, lane = tid & 31, w = tid >> 5;
    int E0 = blockIdx.x * 32;
#pragma unroll
    for (int ee = 0; ee < 4; ee++) {
        int e = w*4 + ee;
        const float* hr = g_h1 + (E0 + e)*DDIM;
#pragma unroll
        for (int t = 0; t < 8; t++) {
            int c = lane + 32*t;
            es[c*36 + e] = hr[c]*g_mv[c] + g_mv[DDIM + c];
        }
    }
    __syncthreads();
    int d = tid;
    float bias = b2[d];
    unsigned long long acc[16];
    unsigned long long bi = pack2(bias, bias);
#pragma unroll
    for (int q = 0; q < 16; q++) acc[q] = bi;
    for (int c = 0; c < 256; c++) {
        float wv = W2[c*DDIM + d];
        unsigned long long w2 = pack2(wv, wv);
        const ulonglong2* f2 = (const ulonglong2*)&es[c*36];
#pragma unroll
        for (int q = 0; q < 8; q++) {
            ulonglong2 u = f2[q];
            ffma2(acc[2*q],   w2, u.x);
            ffma2(acc[2*q+1], w2, u.y);
        }
    }
    float s = 0.f, s2 = 0.f;
#pragma unroll
    for (int q = 0; q < 16; q++) {
        float v0, v1; unpack2(acc[q], v0, v1);
        v0 = fmaxf(v0, 0.f); v1 = fmaxf(v1, 0.f);
        g_h2[(E0 + 2*q  )*DDIM + d] = v0;
        g_h2[(E0 + 2*q+1)*DDIM + d] = v1;
        s += v0 + v1; s2 += v0*v0 + v1*v1;
    }
    atomicAdd(&g_stats[2*DDIM + d], s);
    atomicAdd(&g_stats[3*DDIM + d], s2);
}

// ---------------- K5: BN2-apply + partial max over edges ----------------
__global__ void __launch_bounds__(256) k5_maxpart()
{
    int b = blockIdx.y;
    int ch = blockIdx.x;                       // 0..63, 256 edge-rows each
    int d = threadIdx.x;
    float sc = g_mv[2*DDIM + d], sh = g_mv[3*DDIM + d];
    int base = (b*16384 + ch*256);
    float m = -FLT_MAX;
    for (int e = 0; e < 256; e++)
        m = fmaxf(m, g_h2[(base + e)*DDIM + d]*sc + sh);
    g_pmax[(b*64 + ch)*DDIM + d] = m;
}

// ---------------- K6: final max + head MLP + l2norm ----------------
__global__ void __launch_bounds__(256) k6_final(
    const float* __restrict__ W1, const float* __restrict__ b1,
    const float* __restrict__ W2, const float* __restrict__ b2,
    float* __restrict__ out)
{
    __shared__ float sp[DDIM];
    __shared__ float sh[DDIM];
    __shared__ float red[256];
    int b = blockIdx.x, d = threadIdx.x;
    float m = -FLT_MAX;
    for (int c = 0; c < 64; c++) m = fmaxf(m, g_pmax[(b*64 + c)*DDIM + d]);
    sp[d] = m;
    __syncthreads();
    float a = b1[d];
    for (int k = 0; k < DDIM; k++) a += sp[k]*W1[k*DDIM + d];
    a = fmaxf(a, 0.f);
    sh[d] = a;
    __syncthreads();
    float o = b2[d];
    for (int k = 0; k < DDIM; k++) o += sh[k]*W2[k*DDIM + d];
    o = fmaxf(o, 0.f);
    red[d] = o*o;
    __syncthreads();
    for (int s = 128; s; s >>= 1) { if (d < s) red[d] += red[d + s]; __syncthreads(); }
    float nrm = sqrtf(red[0]);
    out[b*DDIM + d] = o / fmaxf(nrm, 1e-12f);
}

// ---------------- launch ----------------
extern "C" void kernel_launch(void* const* d_in, const int* in_sizes, int n_in,
                              void* d_out, int out_size)
{
    const int*   class_idx   = (const int*)  d_in[0];
    const float* colors      = (const float*)d_in[1];
    const float* positions   = (const float*)d_in[2];
    const float* class_table = (const float*)d_in[3];
    const float* posW1 = (const float*)d_in[4];
    const float* posb1 = (const float*)d_in[5];
    const float* posW2 = (const float*)d_in[6];
    const float* posb2 = (const float*)d_in[7];
    const float* colW1 = (const float*)d_in[8];
    const float* colb1 = (const float*)d_in[9];
    const float* colW2 = (const float*)d_in[10];
    const float* colb2 = (const float*)d_in[11];
    const float* mW    = (const float*)d_in[12];
    const float* mb    = (const float*)d_in[13];
    const float* gW1   = (const float*)d_in[14];
    const float* gb1   = (const float*)d_in[15];
    const float* gg1   = (const float*)d_in[16];
    const float* gbe1  = (const float*)d_in[17];
    const float* gW2   = (const float*)d_in[18];
    const float* gb2   = (const float*)d_in[19];
    const float* gg2   = (const float*)d_in[20];
    const float* gbe2  = (const float*)d_in[21];
    const float* lW1   = (const float*)d_in[22];
    const float* lb1   = (const float*)d_in[23];
    const float* lW2   = (const float*)d_in[24];
    const float* lb2   = (const float*)d_in[25];
    float* out = (float*)d_out;

    cudaFuncSetAttribute(k3_edge1, cudaFuncAttributeMaxDynamicSharedMemorySize, 512*36*4);

    k1_features<<<BB*NN/16, 256>>>(class_idx, colors, positions, class_table,
                                   posW1, posb1, posW2, posb2,
                                   colW1, colb1, colW2, colb2, mW, mb);
    dim3 g2(NN/64, NN/64, BB);
    k2_dist<<<g2, 256>>>();
    k2b_topk<<<BB*NN/8, 256>>>();
    k3_edge1<<<BB*NN/4, 256, 512*36*4>>>(gW1, gb1);
    k_finalize<<<1, 256>>>(0, 0, gg1, gbe1);
    k4_edge2<<<NEDGE/32, 256>>>(gW2, gb2);
    k_finalize<<<1, 256>>>(2*DDIM, 2*DDIM, gg2, gbe2);
    dim3 g5(64, BB);
    k5_maxpart<<<g5, 256>>>();
    k6_final<<<BB, 256>>>(lW1, lb1, lW2, lb2, out);
}

// round 2
// speedup vs baseline: 1.4069x; 1.4069x over previous
#include <cuda_runtime.h>
#include <math.h>
#include <float.h>
#include <stdint.h>

#define BB   8
#define NN   2048
#define DDIM 256
#define KNB  8
#define NNODE (BB*NN)         // 16384
#define NEDGE (NNODE*KNB)     // 131072
#define BN_EPS 1e-5f

// ---------------- scratch ----------------
__device__ float g_x[NNODE*DDIM];          // merged point features  [B*N, D]
__device__ float g_sq[NNODE];              // |x|^2 per point
__device__ int   g_nidx[NNODE*KNB];        // knn indices
__device__ float g_u[NNODE*DDIM];          // x@(W1a-W1b)+b1
__device__ float g_v[NNODE*DDIM];          // x@W1b
__device__ float g_nmax[NNODE*DDIM];       // per-node max of h2 (pre-BN2)
__device__ float g_nmin[NNODE*DDIM];       // per-node min of h2 (pre-BN2)
__device__ float g_stats[4*DDIM];          // [sum1, sqsum1, sum2, sqsum2]
__device__ float g_mv[4*DDIM];             // [scale1, shift1, scale2, shift2]
__device__ float g_pmax[BB*8*DDIM];        // partial max over nodes

// ---------------- helpers ----------------
__device__ __forceinline__ unsigned long long pack2(float lo, float hi) {
    unsigned long long r;
    asm("mov.b64 %0, {%1, %2};" : "=l"(r) : "f"(lo), "f"(hi));
    return r;
}
__device__ __forceinline__ void unpack2(unsigned long long v, float& lo, float& hi) {
    asm("mov.b64 {%0, %1}, %2;" : "=f"(lo), "=f"(hi) : "l"(v));
}
__device__ __forceinline__ void ffma2(unsigned long long& d, unsigned long long a, unsigned long long b) {
    asm("fma.rn.f32x2 %0, %1, %2, %0;" : "+l"(d) : "l"(a), "l"(b));
}
__device__ __forceinline__ float wredsum(float s) {
#pragma unroll
    for (int o = 16; o; o >>= 1) s += __shfl_xor_sync(0xffffffffu, s, o);
    return s;
}
__device__ __forceinline__ bool dless(float d1, int i1, float d2, int i2) {
    return d1 < d2 || (d1 == d2 && i1 < i2);
}

// ---------------- K1: point features + merge GEMM ----------------
__global__ void __launch_bounds__(256) k1_features(
    const int*   __restrict__ class_idx, const float* __restrict__ colors,
    const float* __restrict__ positions, const float* __restrict__ class_table,
    const float* __restrict__ posW1, const float* __restrict__ posb1,
    const float* __restrict__ posW2, const float* __restrict__ posb2,
    const float* __restrict__ colW1, const float* __restrict__ colb1,
    const float* __restrict__ colW2, const float* __restrict__ colb2,
    const float* __restrict__ mW,    const float* __restrict__ mb)
{
    __shared__ __align__(16) float fs[768*16];
    int tid = threadIdx.x, lane = tid & 31, w = tid >> 5;
    int g0 = blockIdx.x * 16;

    if (blockIdx.x == 0)
        for (int i = tid; i < 4*DDIM; i += 256) g_stats[i] = 0.f;

    for (int pp = 0; pp < 2; pp++) {
        int p = w*2 + pp;
        int g = g0 + p;
        int cls = class_idx[g];
        float v[8]; float s = 0.f;
#pragma unroll
        for (int t = 0; t < 8; t++) { v[t] = class_table[cls*DDIM + lane + 32*t]; s += v[t]*v[t]; }
        s = wredsum(s);
        float sc = 1.f / fmaxf(sqrtf(s), 1e-12f);
#pragma unroll
        for (int t = 0; t < 8; t++) fs[(lane + 32*t)*16 + p] = v[t]*sc;

        float a0 = colors[g*3+0], a1 = colors[g*3+1], a2 = colors[g*3+2];
        float h = fmaxf(colb1[lane] + a0*colW1[lane] + a1*colW1[32+lane] + a2*colW1[64+lane], 0.f);
#pragma unroll
        for (int t = 0; t < 8; t++) v[t] = colb2[lane + 32*t];
#pragma unroll 8
        for (int k = 0; k < 32; k++) {
            float hk = __shfl_sync(0xffffffffu, h, k);
#pragma unroll
            for (int t = 0; t < 8; t++) v[t] += hk * colW2[k*DDIM + lane + 32*t];
        }
        s = 0.f;
#pragma unroll
        for (int t = 0; t < 8; t++) { v[t] = fmaxf(v[t], 0.f); s += v[t]*v[t]; }
        s = wredsum(s);
        sc = 1.f / fmaxf(sqrtf(s), 1e-12f);
#pragma unroll
        for (int t = 0; t < 8; t++) fs[(256 + lane + 32*t)*16 + p] = v[t]*sc;

        a0 = positions[g*3+0]; a1 = positions[g*3+1]; a2 = positions[g*3+2];
        h = fmaxf(posb1[lane] + a0*posW1[lane] + a1*posW1[32+lane] + a2*posW1[64+lane], 0.f);
#pragma unroll
        for (int t = 0; t < 8; t++) v[t] = posb2[lane + 32*t];
#pragma unroll 8
        for (int k = 0; k < 32; k++) {
            float hk = __shfl_sync(0xffffffffu, h, k);
#pragma unroll
            for (int t = 0; t < 8; t++) v[t] += hk * posW2[k*DDIM + lane + 32*t];
        }
        s = 0.f;
#pragma unroll
        for (int t = 0; t < 8; t++) { v[t] = fmaxf(v[t], 0.f); s += v[t]*v[t]; }
        s = wredsum(s);
        sc = 1.f / fmaxf(sqrtf(s), 1e-12f);
#pragma unroll
        for (int t = 0; t < 8; t++) fs[(512 + lane + 32*t)*16 + p] = v[t]*sc;
    }
    __syncthreads();

    int d = tid;
    float bv = mb[d];
    unsigned long long acc[8];
    unsigned long long bi = pack2(bv, bv);
#pragma unroll
    for (int q = 0; q < 8; q++) acc[q] = bi;
    for (int c = 0; c < 768; c++) {
        float wv = mW[c*DDIM + d];
        unsigned long long w2 = pack2(wv, wv);
        const ulonglong2* f2 = (const ulonglong2*)&fs[c*16];
#pragma unroll
        for (int q = 0; q < 4; q++) {
            ulonglong2 u = f2[q];
            ffma2(acc[2*q],   w2, u.x);
            ffma2(acc[2*q+1], w2, u.y);
        }
    }
    __syncthreads();
    if (tid < 16) fs[tid] = 0.f;
    __syncthreads();
    float xv[16];
#pragma unroll
    for (int q = 0; q < 8; q++) {
        float v0, v1; unpack2(acc[q], v0, v1);
        v0 = fmaxf(v0, 0.f); v1 = fmaxf(v1, 0.f);
        g_x[(g0 + 2*q  )*DDIM + d] = v0;
        g_x[(g0 + 2*q+1)*DDIM + d] = v1;
        xv[2*q] = v0*v0; xv[2*q+1] = v1*v1;
    }
#pragma unroll
    for (int p = 0; p < 16; p++) {
        float s = wredsum(xv[p]);
        if (lane == 0) atomicAdd(&fs[p], s);
    }
    __syncthreads();
    if (tid < 16) g_sq[g0 + tid] = fs[tid];
}

// ---------------- K2: fused distance gram + top-8 (no dist materialization) ----------------
// Block: 64 rows (i), scan all 2048 j in chunks of 128. Persistent As (64 rows x 256 k).
// smem layout (floats): As[256*64] | BsDs[64*136] (Bs[16][136] then ds[64][136]) | topd[512] | topi[512]
__global__ void __launch_bounds__(256) k2_fused()
{
    extern __shared__ __align__(16) float sm2[];
    float* As   = sm2;                 // 16384
    float* BsDs = sm2 + 16384;         // 8704
    float* topd = sm2 + 16384 + 8704;  // 512
    int*   topi = (int*)(topd + 512);  // 512

    int b = blockIdx.y;
    int i0 = blockIdx.x * 64;
    int tid = threadIdx.x;
    int lane = tid & 31, w = tid >> 5;
    const float* xb = g_x + b*NN*DDIM;

    // load As: x[i0..i0+63][0..255] transposed -> As[k][i] (stride 64)
#pragma unroll
    for (int it = 0; it < 16; it++) {
        int s = tid + it*256;
        int row = s >> 6, f4i = s & 63;
        float4 v = *(const float4*)&xb[(i0 + row)*DDIM + f4i*4];
        As[(f4i*4+0)*64 + row] = v.x;
        As[(f4i*4+1)*64 + row] = v.y;
        As[(f4i*4+2)*64 + row] = v.z;
        As[(f4i*4+3)*64 + row] = v.w;
    }
    for (int s = tid; s < 512; s += 256) { topd[s] = FLT_MAX; topi[s] = 0x7fffffff; }
    __syncthreads();

    int ty = tid >> 4;      // 0..15 -> rows ty*4
    int tx = tid & 15;      // 0..15 -> cols tx*8

    for (int jc = 0; jc < 16; jc++) {
        int j0 = jc * 128;
        unsigned long long acc[4][4];
#pragma unroll
        for (int i = 0; i < 4; i++)
#pragma unroll
            for (int j = 0; j < 4; j++) acc[i][j] = 0ULL;

        for (int kc = 0; kc < DDIM; kc += 16) {
            // load Bs: x[j0..j0+127][kc..kc+15] transposed -> Bs[k][j] (stride 136)
#pragma unroll
            for (int it = 0; it < 2; it++) {
                int s = tid + it*256;
                int jrow = s >> 2, kk4 = s & 3;
                float4 v = *(const float4*)&xb[(j0 + jrow)*DDIM + kc + kk4*4];
                BsDs[(kk4*4+0)*136 + jrow] = v.x;
                BsDs[(kk4*4+1)*136 + jrow] = v.y;
                BsDs[(kk4*4+2)*136 + jrow] = v.z;
                BsDs[(kk4*4+3)*136 + jrow] = v.w;
            }
            __syncthreads();
#pragma unroll
            for (int k = 0; k < 16; k++) {
                float4 a = *(const float4*)&As[(kc+k)*64 + ty*4];
                ulonglong2 b0 = *(const ulonglong2*)&BsDs[k*136 + tx*8];
                ulonglong2 b1 = *(const ulonglong2*)&BsDs[k*136 + tx*8 + 4];
                unsigned long long a0 = pack2(a.x, a.x), a1 = pack2(a.y, a.y);
                unsigned long long a2 = pack2(a.z, a.z), a3 = pack2(a.w, a.w);
                ffma2(acc[0][0], a0, b0.x); ffma2(acc[0][1], a0, b0.y);
                ffma2(acc[0][2], a0, b1.x); ffma2(acc[0][3], a0, b1.y);
                ffma2(acc[1][0], a1, b0.x); ffma2(acc[1][1], a1, b0.y);
                ffma2(acc[1][2], a1, b1.x); ffma2(acc[1][3], a1, b1.y);
                ffma2(acc[2][0], a2, b0.x); ffma2(acc[2][1], a2, b0.y);
                ffma2(acc[2][2], a2, b1.x); ffma2(acc[2][3], a2, b1.y);
                ffma2(acc[3][0], a3, b0.x); ffma2(acc[3][1], a3, b0.y);
                ffma2(acc[3][2], a3, b1.x); ffma2(acc[3][3], a3, b1.y);
            }
            __syncthreads();
        }
        // write dist tile into smem (reuse BsDs region as ds[64][136])
        float sqj[8];
#pragma unroll
        for (int jj = 0; jj < 8; jj++) sqj[jj] = g_sq[b*NN + j0 + tx*8 + jj];
#pragma unroll
        for (int ii = 0; ii < 4; ii++) {
            int il = ty*4 + ii;
            float sqi = g_sq[b*NN + i0 + il];
            float d0, d1, d2, d3, d4, d5, d6, d7;
            unpack2(acc[ii][0], d0, d1); unpack2(acc[ii][1], d2, d3);
            unpack2(acc[ii][2], d4, d5); unpack2(acc[ii][3], d6, d7);
            float4 o0 = { sqi + sqj[0] - 2.f*d0, sqi + sqj[1] - 2.f*d1,
                          sqi + sqj[2] - 2.f*d2, sqi + sqj[3] - 2.f*d3 };
            float4 o1 = { sqi + sqj[4] - 2.f*d4, sqi + sqj[5] - 2.f*d5,
                          sqi + sqj[6] - 2.f*d6, sqi + sqj[7] - 2.f*d7 };
            *(float4*)&BsDs[il*136 + tx*8]     = o0;
            *(float4*)&BsDs[il*136 + tx*8 + 4] = o1;
        }
        __syncthreads();

        // top-k update: warp w owns rows w*8 .. w*8+7
        for (int rr = 0; rr < 8; rr++) {
            int row = w*8 + rr;
            float thr_d = topd[row*8+7]; int thr_i = topi[row*8+7];
#pragma unroll
            for (int t = 0; t < 4; t++) {
                float cd = BsDs[row*136 + lane + 32*t];
                int   cj = j0 + lane + 32*t;
                bool pass = dless(cd, cj, thr_d, thr_i);
                unsigned m = __ballot_sync(0xffffffffu, pass);
                while (m) {
                    int src = __ffs(m) - 1; m &= m - 1;
                    float id = __shfl_sync(0xffffffffu, cd, src);
                    int   ij = __shfl_sync(0xffffffffu, cj, src);
                    if (lane == 0) {
                        if (dless(id, ij, topd[row*8+7], topi[row*8+7])) {
                            int p = 7;
                            while (p > 0 && dless(id, ij, topd[row*8+p-1], topi[row*8+p-1])) {
                                topd[row*8+p] = topd[row*8+p-1];
                                topi[row*8+p] = topi[row*8+p-1];
                                p--;
                            }
                            topd[row*8+p] = id; topi[row*8+p] = ij;
                        }
                    }
                }
                __syncwarp();
                thr_d = topd[row*8+7]; thr_i = topi[row*8+7];
            }
        }
        __syncthreads();
    }
    // write results
    for (int s = tid; s < 512; s += 256) {
        int row = s >> 3, slot = s & 7;
        g_nidx[(b*NN + i0 + row)*KNB + slot] = topi[row*8 + slot];
    }
}

// ---------------- K3a: u = x@(W1a-W1b)+b1, v = x@W1b  (128x128 tiles, 8x8 micro) ----------------
__global__ void __launch_bounds__(256) k3a_uv(const float* __restrict__ W1, const float* __restrict__ b1)
{
    __shared__ __align__(16) float As[16*132];
    __shared__ __align__(16) float Bs[16*132];
    int tid = threadIdx.x;
    int cg = blockIdx.x;                 // 0..3 : virtual col group (0,1 -> u ; 2,3 -> v)
    int r0 = blockIdx.y * 128;
    int m0 = (tid >> 4) * 8;
    int n0 = (tid & 15) * 8;

    unsigned long long acc[8][4];
#pragma unroll
    for (int i = 0; i < 8; i++)
#pragma unroll
        for (int j = 0; j < 4; j++) acc[i][j] = 0ULL;

    for (int kc = 0; kc < DDIM; kc += 16) {
#pragma unroll
        for (int it = 0; it < 2; it++) {
            int s = tid + it*256;
            int row = s >> 2, kk4 = s & 3;
            float4 v = *(const float4*)&g_x[(r0 + row)*DDIM + kc + kk4*4];
            As[(kk4*4+0)*132 + row] = v.x;
            As[(kk4*4+1)*132 + row] = v.y;
            As[(kk4*4+2)*132 + row] = v.z;
            As[(kk4*4+3)*132 + row] = v.w;
        }
#pragma unroll
        for (int it = 0; it < 2; it++) {
            int s = tid + it*256;
            int k = s >> 5, n4 = s & 31;
            int gcol = cg*128 + n4*4;
            float4 wv;
            if (gcol < DDIM) {
                float4 aw = *(const float4*)&W1[(kc+k)*DDIM + gcol];
                float4 bw = *(const float4*)&W1[(kc+k+DDIM)*DDIM + gcol];
                wv.x = aw.x - bw.x; wv.y = aw.y - bw.y;
                wv.z = aw.z - bw.z; wv.w = aw.w - bw.w;
            } else {
                wv = *(const float4*)&W1[(kc+k+DDIM)*DDIM + (gcol - DDIM)];
            }
            Bs[k*132 + n4*4 + 0] = wv.x;
            Bs[k*132 + n4*4 + 1] = wv.y;
            Bs[k*132 + n4*4 + 2] = wv.z;
            Bs[k*132 + n4*4 + 3] = wv.w;
        }
        __syncthreads();
#pragma unroll
        for (int k = 0; k < 16; k++) {
            float4 a0 = *(const float4*)&As[k*132 + m0];
            float4 a1 = *(const float4*)&As[k*132 + m0 + 4];
            ulonglong2 bq0 = *(const ulonglong2*)&Bs[k*132 + n0];
            ulonglong2 bq1 = *(const ulonglong2*)&Bs[k*132 + n0 + 4];
            float av[8] = {a0.x,a0.y,a0.z,a0.w,a1.x,a1.y,a1.z,a1.w};
#pragma unroll
            for (int mi = 0; mi < 8; mi++) {
                unsigned long long ap = pack2(av[mi], av[mi]);
                ffma2(acc[mi][0], ap, bq0.x);
                ffma2(acc[mi][1], ap, bq0.y);
                ffma2(acc[mi][2], ap, bq1.x);
                ffma2(acc[mi][3], ap, bq1.y);
            }
        }
        __syncthreads();
    }
    bool isU = (cg < 2);
    int cbase = (cg & 1)*128 + n0;
#pragma unroll
    for (int mi = 0; mi < 8; mi++) {
        int row = r0 + m0 + mi;
#pragma unroll
        for (int p = 0; p < 4; p++) {
            float v0, v1; unpack2(acc[mi][p], v0, v1);
            int c = cbase + 2*p;
            if (isU) {
                g_u[row*DDIM + c]     = v0 + b1[c];
                g_u[row*DDIM + c + 1] = v1 + b1[c+1];
            } else {
                g_v[row*DDIM + c]     = v0;
                g_v[row*DDIM + c + 1] = v1;
            }
        }
    }
}

// ---------------- K3b: BN1 stats over all edges (h1 = relu(u[i]+v[j])) ----------------
__global__ void __launch_bounds__(256) k3b_stats()
{
    __shared__ int jn[128];
    int tid = threadIdx.x;
    int node0 = blockIdx.x * 16;
    if (tid < 128) jn[tid] = g_nidx[node0*KNB + tid];
    __syncthreads();
    int d = tid;
    float s = 0.f, s2 = 0.f;
#pragma unroll 4
    for (int n = 0; n < 16; n++) {
        float un = g_u[(node0 + n)*DDIM + d];
#pragma unroll
        for (int k = 0; k < 8; k++) {
            int b = (node0 + n) >> 11;
            int j = b*NN + jn[n*8 + k];
            float hv = fmaxf(un + g_v[j*DDIM + d], 0.f);
            s += hv; s2 += hv*hv;
        }
    }
    atomicAdd(&g_stats[d], s);
    atomicAdd(&g_stats[DDIM + d], s2);
}

// ---------------- finalize BN stats -> scale/shift ----------------
__global__ void k_finalize(int si, int mo, const float* __restrict__ gamma, const float* __restrict__ beta)
{
    int d = threadIdx.x;
    float inv = 1.f / (float)NEDGE;
    float m = g_stats[si + d] * inv;
    float v = g_stats[si + DDIM + d] * inv - m*m;
    float rstd = rsqrtf(v + BN_EPS);
    float sc = rstd * gamma[d];
    g_mv[mo + d] = sc;
    g_mv[mo + DDIM + d] = beta[d] - m*sc;
}

// ---------------- K4: recompute h1 -> bn1 -> GEMM2 -> relu -> stats2 + node max/min ----------------
// Block: 8 nodes = 64 edges x 256 cols. Thread: eg = tid>>5 owns node eg's 8 edges, dg = tid&31 -> 8 cols.
__global__ void __launch_bounds__(256) k4_edge2(const float* __restrict__ W2, const float* __restrict__ b2)
{
    __shared__ __align__(16) float Ws[32*260];   // W2 k-slab (reused as stats buffers)
    __shared__ __align__(16) float es[32*68];    // edge activations [k][e]
    __shared__ int jn[64];
    int tid = threadIdx.x;
    int eg = tid >> 5;      // 0..7  (node within block)
    int dg = tid & 31;      // 0..31 (col group of 8)
    int kk = tid & 31;
    int node0 = blockIdx.x * 8;

    if (tid < 64) jn[tid] = g_nidx[node0*KNB + tid];
    __syncthreads();
    int bofs = (node0 >> 11) * NN;     // block never spans batches (8 | 2048)

    unsigned long long acc[8][4];
    {
        float4 w0 = *(const float4*)&b2[dg*8];
        float4 w1 = *(const float4*)&b2[dg*8 + 4];
        unsigned long long i0 = pack2(w0.x, w0.y), i1 = pack2(w0.z, w0.w);
        unsigned long long i2 = pack2(w1.x, w1.y), i3 = pack2(w1.z, w1.w);
#pragma unroll
        for (int e = 0; e < 8; e++) { acc[e][0]=i0; acc[e][1]=i1; acc[e][2]=i2; acc[e][3]=i3; }
    }

    for (int kc = 0; kc < DDIM; kc += 32) {
        // stage W2 slab [32][256]
#pragma unroll
        for (int it = 0; it < 8; it++) {
            int s = tid + it*256;
            int k = s >> 6, d4 = s & 63;
            float4 v = *(const float4*)&W2[(kc+k)*DDIM + d4*4];
            Ws[k*260 + d4*4 + 0] = v.x;
            Ws[k*260 + d4*4 + 1] = v.y;
            Ws[k*260 + d4*4 + 2] = v.z;
            Ws[k*260 + d4*4 + 3] = v.w;
        }
        // compute es[k][e] = relu(u+v)*sc1+sh1 for k = kk, e = eg*8..eg*8+7
        {
            float sc1 = g_mv[kc + kk], sh1 = g_mv[DDIM + kc + kk];
            float uv = g_u[(node0 + eg)*DDIM + kc + kk];
#pragma unroll
            for (int i = 0; i < 8; i++) {
                int j = bofs + jn[eg*8 + i];
                float hv = fmaxf(uv + g_v[j*DDIM + kc + kk], 0.f);
                es[kk*68 + eg*8 + i] = hv*sc1 + sh1;
            }
        }
        __syncthreads();
#pragma unroll
        for (int k = 0; k < 32; k++) {
            float4 a0 = *(const float4*)&es[k*68 + eg*8];
            float4 a1 = *(const float4*)&es[k*68 + eg*8 + 4];
            ulonglong2 bq0 = *(const ulonglong2*)&Ws[k*260 + dg*8];
            ulonglong2 bq1 = *(const ulonglong2*)&Ws[k*260 + dg*8 + 4];
            float av[8] = {a0.x,a0.y,a0.z,a0.w,a1.x,a1.y,a1.z,a1.w};
#pragma unroll
            for (int e = 0; e < 8; e++) {
                unsigned long long ap = pack2(av[e], av[e]);
                ffma2(acc[e][0], ap, bq0.x);
                ffma2(acc[e][1], ap, bq0.y);
                ffma2(acc[e][2], ap, bq1.x);
                ffma2(acc[e][3], ap, bq1.y);
            }
        }
        __syncthreads();
    }

    // epilogue: relu, per-node (== per-thread-eg) max/min, stats sums
    float* sb = Ws;            // [8][256] sums
    float* sq = Ws + 2048;     // [8][256] sq sums
    int node = node0 + eg;
#pragma unroll
    for (int p = 0; p < 4; p++) {
        float mx0 = -FLT_MAX, mx1 = -FLT_MAX, mn0 = FLT_MAX, mn1 = FLT_MAX;
        float s0 = 0.f, s1 = 0.f, q0 = 0.f, q1 = 0.f;
#pragma unroll
        for (int e = 0; e < 8; e++) {
            float v0, v1; unpack2(acc[e][p], v0, v1);
            v0 = fmaxf(v0, 0.f); v1 = fmaxf(v1, 0.f);
            mx0 = fmaxf(mx0, v0); mx1 = fmaxf(mx1, v1);
            mn0 = fminf(mn0, v0); mn1 = fminf(mn1, v1);
            s0 += v0; s1 += v1; q0 += v0*v0; q1 += v1*v1;
        }
        int c = dg*8 + 2*p;
        g_nmax[node*DDIM + c]     = mx0;
        g_nmax[node*DDIM + c + 1] = mx1;
        g_nmin[node*DDIM + c]     = mn0;
        g_nmin[node*DDIM + c + 1] = mn1;
        sb[eg*256 + c] = s0; sb[eg*256 + c + 1] = s1;
        sq[eg*256 + c] = q0; sq[eg*256 + c + 1] = q1;
    }
    __syncthreads();
    int d = tid;
    float ts = 0.f, tq = 0.f;
#pragma unroll
    for (int e = 0; e < 8; e++) { ts += sb[e*256 + d]; tq += sq[e*256 + d]; }
    atomicAdd(&g_stats[2*DDIM + d], ts);
    atomicAdd(&g_stats[3*DDIM + d], tq);
}

// ---------------- K5: bn2-apply on node extrema + partial max over nodes ----------------
__global__ void __launch_bounds__(256) k5_maxpart()
{
    int b = blockIdx.y;
    int ch = blockIdx.x;        // 0..7, 256 nodes each
    int d = threadIdx.x;
    float sc = g_mv[2*DDIM + d], sh = g_mv[3*DDIM + d];
    const float* src = (sc > 0.f) ? g_nmax : g_nmin;
    int base = b*NN + ch*256;
    float m = -FLT_MAX;
    for (int n = 0; n < 256; n++)
        m = fmaxf(m, src[(base + n)*DDIM + d]);
    g_pmax[(b*8 + ch)*DDIM + d] = m*sc + sh;
}

// ---------------- K6: final max + head MLP + l2norm ----------------
__global__ void __launch_bounds__(256) k6_final(
    const float* __restrict__ W1, const float* __restrict__ b1,
    const float* __restrict__ W2, const float* __restrict__ b2,
    float* __restrict__ out)
{
    __shared__ float sp[DDIM];
    __shared__ float sh[DDIM];
    __shared__ float red[256];
    int b = blockIdx.x, d = threadIdx.x;
    float m = -FLT_MAX;
    for (int c = 0; c < 8; c++) m = fmaxf(m, g_pmax[(b*8 + c)*DDIM + d]);
    sp[d] = m;
    __syncthreads();
    float a = b1[d];
    for (int k = 0; k < DDIM; k++) a += sp[k]*W1[k*DDIM + d];
    a = fmaxf(a, 0.f);
    sh[d] = a;
    __syncthreads();
    float o = b2[d];
    for (int k = 0; k < DDIM; k++) o += sh[k]*W2[k*DDIM + d];
    o = fmaxf(o, 0.f);
    red[d] = o*o;
    __syncthreads();
    for (int s = 128; s; s >>= 1) { if (d < s) red[d] += red[d + s]; __syncthreads(); }
    float nrm = sqrtf(red[0]);
    out[b*DDIM + d] = o / fmaxf(nrm, 1e-12f);
}

// ---------------- launch ----------------
extern "C" void kernel_launch(void* const* d_in, const int* in_sizes, int n_in,
                              void* d_out, int out_size)
{
    const int*   class_idx   = (const int*)  d_in[0];
    const float* colors      = (const float*)d_in[1];
    const float* positions   = (const float*)d_in[2];
    const float* class_table = (const float*)d_in[3];
    const float* posW1 = (const float*)d_in[4];
    const float* posb1 = (const float*)d_in[5];
    const float* posW2 = (const float*)d_in[6];
    const float* posb2 = (const float*)d_in[7];
    const float* colW1 = (const float*)d_in[8];
    const float* colb1 = (const float*)d_in[9];
    const float* colW2 = (const float*)d_in[10];
    const float* colb2 = (const float*)d_in[11];
    const float* mW    = (const float*)d_in[12];
    const float* mb    = (const float*)d_in[13];
    const float* gW1   = (const float*)d_in[14];
    const float* gb1   = (const float*)d_in[15];
    const float* gg1   = (const float*)d_in[16];
    const float* gbe1  = (const float*)d_in[17];
    const float* gW2   = (const float*)d_in[18];
    const float* gb2   = (const float*)d_in[19];
    const float* gg2   = (const float*)d_in[20];
    const float* gbe2  = (const float*)d_in[21];
    const float* lW1   = (const float*)d_in[22];
    const float* lb1   = (const float*)d_in[23];
    const float* lW2   = (const float*)d_in[24];
    const float* lb2   = (const float*)d_in[25];
    float* out = (float*)d_out;

    static int cfg_done = 0;
    int k2_smem = (16384 + 8704 + 512) * 4 + 512 * 4;
    if (!cfg_done) {
        cudaFuncSetAttribute(k2_fused, cudaFuncAttributeMaxDynamicSharedMemorySize, k2_smem);
        cfg_done = 1;
    }

    k1_features<<<NNODE/16, 256>>>(class_idx, colors, positions, class_table,
                                   posW1, posb1, posW2, posb2,
                                   colW1, colb1, colW2, colb2, mW, mb);
    dim3 g2(NN/64, BB);
    k2_fused<<<g2, 256, k2_smem>>>();
    dim3 g3(4, NNODE/128);
    k3a_uv<<<g3, 256>>>(gW1, gb1);
    k3b_stats<<<NNODE/16, 256>>>();
    k_finalize<<<1, 256>>>(0, 0, gg1, gbe1);
    k4_edge2<<<NNODE/8, 256>>>(gW2, gb2);
    k_finalize<<<1, 256>>>(2*DDIM, 2*DDIM, gg2, gbe2);
    dim3 g5(8, BB);
    k5_maxpart<<<g5, 256>>>();
    k6_final<<<BB, 256>>>(lW1, lb1, lW2, lb2, out);
}

// round 4
// speedup vs baseline: 1.7385x; 1.2357x over previous
#include <cuda_runtime.h>
#include <cuda_bf16.h>
#include <math.h>
#include <float.h>
#include <stdint.h>

#define BB   8
#define NN   2048
#define DDIM 256
#define KNB  8
#define NNODE (BB*NN)         // 16384
#define NEDGE (NNODE*KNB)     // 131072
#define BN_EPS 1e-5f

// ---------------- scratch ----------------
__device__ float g_x[NNODE*DDIM];          // merged point features  [B*N, D]
__device__ __nv_bfloat16 g_xh[NNODE*DDIM]; // bf16 hi split of x
__device__ __nv_bfloat16 g_xl[NNODE*DDIM]; // bf16 lo split of x
__device__ float g_sq[NNODE];              // |x|^2 per point
__device__ int   g_nidx[NNODE*KNB];        // knn indices
__device__ float g_u[NNODE*DDIM];          // x@(W1a-W1b)+b1
__device__ float g_v[NNODE*DDIM];          // x@W1b
__device__ float g_nmax[NNODE*DDIM];       // per-node max of h2 (pre-BN2)
__device__ float g_nmin[NNODE*DDIM];       // per-node min of h2 (pre-BN2)
__device__ float g_stats[4*DDIM];          // [sum1, sqsum1, sum2, sqsum2]
__device__ float g_mv[4*DDIM];             // [scale1, shift1, scale2, shift2]
__device__ float g_pmax[BB*8*DDIM];        // partial max over nodes

// ---------------- scalar helpers ----------------
__device__ __forceinline__ unsigned long long pack2(float lo, float hi) {
    unsigned long long r;
    asm("mov.b64 %0, {%1, %2};" : "=l"(r) : "f"(lo), "f"(hi));
    return r;
}
__device__ __forceinline__ void unpack2(unsigned long long v, float& lo, float& hi) {
    asm("mov.b64 {%0, %1}, %2;" : "=f"(lo), "=f"(hi) : "l"(v));
}
__device__ __forceinline__ void ffma2(unsigned long long& d, unsigned long long a, unsigned long long b) {
    asm("fma.rn.f32x2 %0, %1, %2, %0;" : "+l"(d) : "l"(a), "l"(b));
}
__device__ __forceinline__ float wredsum(float s) {
#pragma unroll
    for (int o = 16; o; o >>= 1) s += __shfl_xor_sync(0xffffffffu, s, o);
    return s;
}
__device__ __forceinline__ bool dless(float d1, int i1, float d2, int i2) {
    return d1 < d2 || (d1 == d2 && i1 < i2);
}

// warp-level bf16 MMA (HMMA fallback path on sm_103): D[16x8] += A[16x16] * B[16x8]
// A row-major [m][k], B "col-major" = row-major [n][k]. fp32 accumulate.
__device__ __forceinline__ void mma16816(float* c, uint32_t a0, uint32_t a1, uint32_t a2, uint32_t a3,
                                         uint32_t b0, uint32_t b1) {
    asm volatile(
        "mma.sync.aligned.m16n8k16.row.col.f32.bf16.bf16.f32 "
        "{%0,%1,%2,%3}, {%4,%5,%6,%7}, {%8,%9}, {%0,%1,%2,%3};"
        : "+f"(c[0]), "+f"(c[1]), "+f"(c[2]), "+f"(c[3])
        : "r"(a0), "r"(a1), "r"(a2), "r"(a3), "r"(b0), "r"(b1));
}

// ---------------- K1: point features + merge GEMM ----------------
__global__ void __launch_bounds__(256) k1_features(
    const int*   __restrict__ class_idx, const float* __restrict__ colors,
    const float* __restrict__ positions, const float* __restrict__ class_table,
    const float* __restrict__ posW1, const float* __restrict__ posb1,
    const float* __restrict__ posW2, const float* __restrict__ posb2,
    const float* __restrict__ colW1, const float* __restrict__ colb1,
    const float* __restrict__ colW2, const float* __restrict__ colb2,
    const float* __restrict__ mW,    const float* __restrict__ mb)
{
    __shared__ __align__(16) float fs[768*16];
    int tid = threadIdx.x, lane = tid & 31, w = tid >> 5;
    int g0 = blockIdx.x * 16;

    if (blockIdx.x == 0)
        for (int i = tid; i < 4*DDIM; i += 256) g_stats[i] = 0.f;

    for (int pp = 0; pp < 2; pp++) {
        int p = w*2 + pp;
        int g = g0 + p;
        int cls = class_idx[g];
        float v[8]; float s = 0.f;
#pragma unroll
        for (int t = 0; t < 8; t++) { v[t] = class_table[cls*DDIM + lane + 32*t]; s += v[t]*v[t]; }
        s = wredsum(s);
        float sc = 1.f / fmaxf(sqrtf(s), 1e-12f);
#pragma unroll
        for (int t = 0; t < 8; t++) fs[(lane + 32*t)*16 + p] = v[t]*sc;

        float a0 = colors[g*3+0], a1 = colors[g*3+1], a2 = colors[g*3+2];
        float h = fmaxf(colb1[lane] + a0*colW1[lane] + a1*colW1[32+lane] + a2*colW1[64+lane], 0.f);
#pragma unroll
        for (int t = 0; t < 8; t++) v[t] = colb2[lane + 32*t];
#pragma unroll 8
        for (int k = 0; k < 32; k++) {
            float hk = __shfl_sync(0xffffffffu, h, k);
#pragma unroll
            for (int t = 0; t < 8; t++) v[t] += hk * colW2[k*DDIM + lane + 32*t];
        }
        s = 0.f;
#pragma unroll
        for (int t = 0; t < 8; t++) { v[t] = fmaxf(v[t], 0.f); s += v[t]*v[t]; }
        s = wredsum(s);
        sc = 1.f / fmaxf(sqrtf(s), 1e-12f);
#pragma unroll
        for (int t = 0; t < 8; t++) fs[(256 + lane + 32*t)*16 + p] = v[t]*sc;

        a0 = positions[g*3+0]; a1 = positions[g*3+1]; a2 = positions[g*3+2];
        h = fmaxf(posb1[lane] + a0*posW1[lane] + a1*posW1[32+lane] + a2*posW1[64+lane], 0.f);
#pragma unroll
        for (int t = 0; t < 8; t++) v[t] = posb2[lane + 32*t];
#pragma unroll 8
        for (int k = 0; k < 32; k++) {
            float hk = __shfl_sync(0xffffffffu, h, k);
#pragma unroll
            for (int t = 0; t < 8; t++) v[t] += hk * posW2[k*DDIM + lane + 32*t];
        }
        s = 0.f;
#pragma unroll
        for (int t = 0; t < 8; t++) { v[t] = fmaxf(v[t], 0.f); s += v[t]*v[t]; }
        s = wredsum(s);
        sc = 1.f / fmaxf(sqrtf(s), 1e-12f);
#pragma unroll
        for (int t = 0; t < 8; t++) fs[(512 + lane + 32*t)*16 + p] = v[t]*sc;
    }
    __syncthreads();

    int d = tid;
    float bv = mb[d];
    unsigned long long acc[8];
    unsigned long long bi = pack2(bv, bv);
#pragma unroll
    for (int q = 0; q < 8; q++) acc[q] = bi;
    for (int c = 0; c < 768; c++) {
        float wv = mW[c*DDIM + d];
        unsigned long long w2 = pack2(wv, wv);
        const ulonglong2* f2 = (const ulonglong2*)&fs[c*16];
#pragma unroll
        for (int q = 0; q < 4; q++) {
            ulonglong2 u = f2[q];
            ffma2(acc[2*q],   w2, u.x);
            ffma2(acc[2*q+1], w2, u.y);
        }
    }
    __syncthreads();
    if (tid < 16) fs[tid] = 0.f;
    __syncthreads();
    float xv[16];
#pragma unroll
    for (int q = 0; q < 8; q++) {
        float v0, v1; unpack2(acc[q], v0, v1);
        v0 = fmaxf(v0, 0.f); v1 = fmaxf(v1, 0.f);
        g_x[(g0 + 2*q  )*DDIM + d] = v0;
        g_x[(g0 + 2*q+1)*DDIM + d] = v1;
        xv[2*q] = v0*v0; xv[2*q+1] = v1*v1;
    }
#pragma unroll
    for (int p = 0; p < 16; p++) {
        float s = wredsum(xv[p]);
        if (lane == 0) atomicAdd(&fs[p], s);
    }
    __syncthreads();
    if (tid < 16) g_sq[g0 + tid] = fs[tid];
}

// ---------------- K1b: split x into bf16 hi/lo ----------------
__global__ void __launch_bounds__(256) k1b_split()
{
    int i = (blockIdx.x*256 + threadIdx.x)*4;
    float4 v = *(const float4*)&g_x[i];
    __nv_bfloat16 h0 = __float2bfloat16(v.x);
    __nv_bfloat16 h1 = __float2bfloat16(v.y);
    __nv_bfloat16 h2 = __float2bfloat16(v.z);
    __nv_bfloat16 h3 = __float2bfloat16(v.w);
    __nv_bfloat16 l0 = __float2bfloat16(v.x - __bfloat162float(h0));
    __nv_bfloat16 l1 = __float2bfloat16(v.y - __bfloat162float(h1));
    __nv_bfloat16 l2 = __float2bfloat16(v.z - __bfloat162float(h2));
    __nv_bfloat16 l3 = __float2bfloat16(v.w - __bfloat162float(h3));
    __nv_bfloat162 hp0; hp0.x = h0; hp0.y = h1;
    __nv_bfloat162 hp1; hp1.x = h2; hp1.y = h3;
    __nv_bfloat162 lp0; lp0.x = l0; lp0.y = l1;
    __nv_bfloat162 lp1; lp1.x = l2; lp1.y = l3;
    *(__nv_bfloat162*)&g_xh[i]     = hp0;
    *(__nv_bfloat162*)&g_xh[i + 2] = hp1;
    *(__nv_bfloat162*)&g_xl[i]     = lp0;
    *(__nv_bfloat162*)&g_xl[i + 2] = lp1;
}

// ---------------- K2: HMMA bf16-split gram + fused top-8 ----------------
// CTA = 128 i-rows of one batch (grid 16 x 8 = 128 CTAs, one wave).
// A (hi+lo) persistent in smem; B streamed per 128-j chunk in 64-k slabs.
// Warp w owns output rows w*16..w*16+15 (full 128 cols in C regs).
// smem bytes:
//   [0)      sq_i   128 f        = 512
//   [512)    sq_j   128 f        = 512
//   [1024)   topd   1024 f       = 4096
//   [5120)   topi   1024 i       = 4096
//   [9216)   Ah     128*264 bf16 = 67584
//   [76800)  Al     128*264 bf16 = 67584
//   [144384) Bh     128*72 bf16  = 18432   (reused as dist[128][68] f = 34816)
//   [162816) Bl     128*72 bf16  = 18432
//   total 181248
#define K2_SMEM_SZ 181248

__global__ void __launch_bounds__(256) k2_mma()
{
    extern __shared__ __align__(16) char sm[];
    float* sq_i_s = (float*)(sm + 0);
    float* sq_j_s = (float*)(sm + 512);
    float* topd   = (float*)(sm + 1024);
    int*   topi   = (int*)(sm + 5120);
    __nv_bfloat16* Ah = (__nv_bfloat16*)(sm + 9216);
    __nv_bfloat16* Al = (__nv_bfloat16*)(sm + 76800);
    __nv_bfloat16* Bh = (__nv_bfloat16*)(sm + 144384);
    __nv_bfloat16* Bl = (__nv_bfloat16*)(sm + 162816);
    float* dist = (float*)(sm + 144384);       // overlays Bh/Bl after K accumulation

    int tid = threadIdx.x, lane = tid & 31, w = tid >> 5;
    int b = blockIdx.y;
    int i0 = blockIdx.x * 128;
    int nb = b*NN;

    for (int s = tid; s < 1024; s += 256) { topd[s] = FLT_MAX; topi[s] = 0x7fffffff; }
    if (tid < 128) sq_i_s[tid] = g_sq[nb + i0 + tid];

    // stage A hi/lo: [128][264] row-major halves
    for (int s = tid; s < 128*32; s += 256) {
        int r = s >> 5, kq = (s & 31) * 8;
        int gofs = (nb + i0 + r)*DDIM + kq;
        *(uint4*)&Ah[r*264 + kq] = *(const uint4*)&g_xh[gofs];
        *(uint4*)&Al[r*264 + kq] = *(const uint4*)&g_xl[gofs];
    }
    __syncthreads();

    int m0 = w*16;
    int arow = lane >> 2;            // 0..7
    int kq2  = (lane & 3) * 2;       // 0,2,4,6

    float c[16][4];
#pragma unroll
    for (int nt = 0; nt < 16; nt++)
#pragma unroll
        for (int q = 0; q < 4; q++) c[nt][q] = 0.f;

    for (int jc = 0; jc < 16; jc++) {
        int j0 = jc * 128;
        if (tid < 128) sq_j_s[tid] = g_sq[nb + j0 + tid];

        for (int ks = 0; ks < 4; ks++) {
            // stage B slab: rows j0..j0+127, feats ks*64..ks*64+63
            for (int s = tid; s < 128*8; s += 256) {
                int r = s >> 3, kq = (s & 7) * 8;
                int gofs = (nb + j0 + r)*DDIM + ks*64 + kq;
                *(uint4*)&Bh[r*72 + kq] = *(const uint4*)&g_xh[gofs];
                *(uint4*)&Bl[r*72 + kq] = *(const uint4*)&g_xl[gofs];
            }
            __syncthreads();
#pragma unroll
            for (int k0 = 0; k0 < 64; k0 += 16) {
                int ka = ks*64 + k0 + kq2;
                uint32_t ah0 = *(const uint32_t*)&Ah[(m0+arow  )*264 + ka];
                uint32_t ah1 = *(const uint32_t*)&Ah[(m0+arow+8)*264 + ka];
                uint32_t ah2 = *(const uint32_t*)&Ah[(m0+arow  )*264 + ka + 8];
                uint32_t ah3 = *(const uint32_t*)&Ah[(m0+arow+8)*264 + ka + 8];
                uint32_t al0 = *(const uint32_t*)&Al[(m0+arow  )*264 + ka];
                uint32_t al1 = *(const uint32_t*)&Al[(m0+arow+8)*264 + ka];
                uint32_t al2 = *(const uint32_t*)&Al[(m0+arow  )*264 + ka + 8];
                uint32_t al3 = *(const uint32_t*)&Al[(m0+arow+8)*264 + ka + 8];
#pragma unroll
                for (int nt = 0; nt < 16; nt++) {
                    int br = nt*8 + arow;
                    int kb = k0 + kq2;
                    uint32_t bh0 = *(const uint32_t*)&Bh[br*72 + kb];
                    uint32_t bh1 = *(const uint32_t*)&Bh[br*72 + kb + 8];
                    uint32_t bl0 = *(const uint32_t*)&Bl[br*72 + kb];
                    uint32_t bl1 = *(const uint32_t*)&Bl[br*72 + kb + 8];
                    mma16816(c[nt], ah0, ah1, ah2, ah3, bh0, bh1);
                    mma16816(c[nt], ah0, ah1, ah2, ah3, bl0, bl1);
                    mma16816(c[nt], al0, al1, al2, al3, bh0, bh1);
                }
            }
            __syncthreads();
        }

        // epilogue: two halves of 64 cols; dist overlays the B region
        float sqi0 = sq_i_s[m0 + arow];
        float sqi1 = sq_i_s[m0 + arow + 8];
#pragma unroll
        for (int h = 0; h < 2; h++) {
#pragma unroll
            for (int nt8 = 0; nt8 < 8; nt8++) {
                int nt = h*8 + nt8;
                int colj = nt*8 + kq2;                // 0..127 within chunk
                float sj0 = sq_j_s[colj], sj1 = sq_j_s[colj + 1];
                int cl = nt8*8 + kq2;                 // 0..63 within half
                float2 o0 = { sqi0 + sj0 - 2.f*c[nt][0], sqi0 + sj1 - 2.f*c[nt][1] };
                float2 o1 = { sqi1 + sj0 - 2.f*c[nt][2], sqi1 + sj1 - 2.f*c[nt][3] };
                *(float2*)&dist[(m0 + arow    )*68 + cl] = o0;
                *(float2*)&dist[(m0 + arow + 8)*68 + cl] = o1;
            }
            __syncthreads();
            for (int rr = 0; rr < 16; rr++) {
                int row = w*16 + rr;
#pragma unroll
                for (int ps = 0; ps < 2; ps++) {
                    float cd = dist[row*68 + ps*32 + lane];
                    int   cj = j0 + h*64 + ps*32 + lane;
                    float thr_d = topd[row*8+7]; int thr_i = topi[row*8+7];
                    bool pass = dless(cd, cj, thr_d, thr_i);
                    unsigned m = __ballot_sync(0xffffffffu, pass);
                    while (m) {
                        int src = __ffs(m) - 1; m &= m - 1;
                        float id = __shfl_sync(0xffffffffu, cd, src);
                        int   ij = __shfl_sync(0xffffffffu, cj, src);
                        if (lane == 0) {
                            if (dless(id, ij, topd[row*8+7], topi[row*8+7])) {
                                int p = 7;
                                while (p > 0 && dless(id, ij, topd[row*8+p-1], topi[row*8+p-1])) {
                                    topd[row*8+p] = topd[row*8+p-1];
                                    topi[row*8+p] = topi[row*8+p-1];
                                    p--;
                                }
                                topd[row*8+p] = id; topi[row*8+p] = ij;
                            }
                        }
                    }
                    __syncwarp();
                }
            }
            __syncthreads();
        }
#pragma unroll
        for (int nt = 0; nt < 16; nt++)
#pragma unroll
            for (int q = 0; q < 4; q++) c[nt][q] = 0.f;
    }

    for (int s = tid; s < 1024; s += 256)
        g_nidx[(nb + i0 + (s >> 3))*KNB + (s & 7)] = topi[s];
}

// ---------------- K3a: u = x@(W1a-W1b)+b1, v = x@W1b ----------------
__global__ void __launch_bounds__(256) k3a_uv(const float* __restrict__ W1, const float* __restrict__ b1)
{
    __shared__ __align__(16) float As[16*132];
    __shared__ __align__(16) float Bs[16*132];
    int tid = threadIdx.x;
    int cg = blockIdx.x;
    int r0 = blockIdx.y * 128;
    int m0 = (tid >> 4) * 8;
    int n0 = (tid & 15) * 8;

    unsigned long long acc[8][4];
#pragma unroll
    for (int i = 0; i < 8; i++)
#pragma unroll
        for (int j = 0; j < 4; j++) acc[i][j] = 0ULL;

    for (int kc = 0; kc < DDIM; kc += 16) {
#pragma unroll
        for (int it = 0; it < 2; it++) {
            int s = tid + it*256;
            int row = s >> 2, kk4 = s & 3;
            float4 v = *(const float4*)&g_x[(r0 + row)*DDIM + kc + kk4*4];
            As[(kk4*4+0)*132 + row] = v.x;
            As[(kk4*4+1)*132 + row] = v.y;
            As[(kk4*4+2)*132 + row] = v.z;
            As[(kk4*4+3)*132 + row] = v.w;
        }
#pragma unroll
        for (int it = 0; it < 2; it++) {
            int s = tid + it*256;
            int k = s >> 5, n4 = s & 31;
            int gcol = cg*128 + n4*4;
            float4 wv;
            if (gcol < DDIM) {
                float4 aw = *(const float4*)&W1[(kc+k)*DDIM + gcol];
                float4 bw = *(const float4*)&W1[(kc+k+DDIM)*DDIM + gcol];
                wv.x = aw.x - bw.x; wv.y = aw.y - bw.y;
                wv.z = aw.z - bw.z; wv.w = aw.w - bw.w;
            } else {
                wv = *(const float4*)&W1[(kc+k+DDIM)*DDIM + (gcol - DDIM)];
            }
            Bs[k*132 + n4*4 + 0] = wv.x;
            Bs[k*132 + n4*4 + 1] = wv.y;
            Bs[k*132 + n4*4 + 2] = wv.z;
            Bs[k*132 + n4*4 + 3] = wv.w;
        }
        __syncthreads();
#pragma unroll
        for (int k = 0; k < 16; k++) {
            float4 a0 = *(const float4*)&As[k*132 + m0];
            float4 a1 = *(const float4*)&As[k*132 + m0 + 4];
            ulonglong2 bq0 = *(const ulonglong2*)&Bs[k*132 + n0];
            ulonglong2 bq1 = *(const ulonglong2*)&Bs[k*132 + n0 + 4];
            float av[8] = {a0.x,a0.y,a0.z,a0.w,a1.x,a1.y,a1.z,a1.w};
#pragma unroll
            for (int mi = 0; mi < 8; mi++) {
                unsigned long long ap = pack2(av[mi], av[mi]);
                ffma2(acc[mi][0], ap, bq0.x);
                ffma2(acc[mi][1], ap, bq0.y);
                ffma2(acc[mi][2], ap, bq1.x);
                ffma2(acc[mi][3], ap, bq1.y);
            }
        }
        __syncthreads();
    }
    bool isU = (cg < 2);
    int cbase = (cg & 1)*128 + n0;
#pragma unroll
    for (int mi = 0; mi < 8; mi++) {
        int row = r0 + m0 + mi;
#pragma unroll
        for (int p = 0; p < 4; p++) {
            float v0, v1; unpack2(acc[mi][p], v0, v1);
            int c = cbase + 2*p;
            if (isU) {
                g_u[row*DDIM + c]     = v0 + b1[c];
                g_u[row*DDIM + c + 1] = v1 + b1[c+1];
            } else {
                g_v[row*DDIM + c]     = v0;
                g_v[row*DDIM + c + 1] = v1;
            }
        }
    }
}

// ---------------- K3b: BN1 stats over all edges ----------------
__global__ void __launch_bounds__(256) k3b_stats()
{
    __shared__ int jn[128];
    int tid = threadIdx.x;
    int node0 = blockIdx.x * 16;
    if (tid < 128) jn[tid] = g_nidx[node0*KNB + tid];
    __syncthreads();
    int d = tid;
    float s = 0.f, s2 = 0.f;
#pragma unroll 4
    for (int n = 0; n < 16; n++) {
        float un = g_u[(node0 + n)*DDIM + d];
#pragma unroll
        for (int k = 0; k < 8; k++) {
            int b = (node0 + n) >> 11;
            int j = b*NN + jn[n*8 + k];
            float hv = fmaxf(un + g_v[j*DDIM + d], 0.f);
            s += hv; s2 += hv*hv;
        }
    }
    atomicAdd(&g_stats[d], s);
    atomicAdd(&g_stats[DDIM + d], s2);
}

// ---------------- finalize BN stats ----------------
__global__ void k_finalize(int si, int mo, const float* __restrict__ gamma, const float* __restrict__ beta)
{
    int d = threadIdx.x;
    float inv = 1.f / (float)NEDGE;
    float m = g_stats[si + d] * inv;
    float v = g_stats[si + DDIM + d] * inv - m*m;
    float rstd = rsqrtf(v + BN_EPS);
    float sc = rstd * gamma[d];
    g_mv[mo + d] = sc;
    g_mv[mo + DDIM + d] = beta[d] - m*sc;
}

// ---------------- K4: recompute h1 -> bn1 -> GEMM2 -> relu -> stats2 + node max/min ----------------
__global__ void __launch_bounds__(256) k4_edge2(const float* __restrict__ W2, const float* __restrict__ b2)
{
    __shared__ __align__(16) float Ws[32*260];
    __shared__ __align__(16) float es[32*68];
    __shared__ int jn[64];
    int tid = threadIdx.x;
    int eg = tid >> 5;
    int dg = tid & 31;
    int kk = tid & 31;
    int node0 = blockIdx.x * 8;

    if (tid < 64) jn[tid] = g_nidx[node0*KNB + tid];
    __syncthreads();
    int bofs = (node0 >> 11) * NN;

    unsigned long long acc[8][4];
    {
        float4 w0 = *(const float4*)&b2[dg*8];
        float4 w1 = *(const float4*)&b2[dg*8 + 4];
        unsigned long long i0 = pack2(w0.x, w0.y), i1 = pack2(w0.z, w0.w);
        unsigned long long i2 = pack2(w1.x, w1.y), i3 = pack2(w1.z, w1.w);
#pragma unroll
        for (int e = 0; e < 8; e++) { acc[e][0]=i0; acc[e][1]=i1; acc[e][2]=i2; acc[e][3]=i3; }
    }

    for (int kc = 0; kc < DDIM; kc += 32) {
#pragma unroll
        for (int it = 0; it < 8; it++) {
            int s = tid + it*256;
            int k = s >> 6, d4 = s & 63;
            float4 v = *(const float4*)&W2[(kc+k)*DDIM + d4*4];
            Ws[k*260 + d4*4 + 0] = v.x;
            Ws[k*260 + d4*4 + 1] = v.y;
            Ws[k*260 + d4*4 + 2] = v.z;
            Ws[k*260 + d4*4 + 3] = v.w;
        }
        {
            float sc1 = g_mv[kc + kk], sh1 = g_mv[DDIM + kc + kk];
            float uv = g_u[(node0 + eg)*DDIM + kc + kk];
#pragma unroll
            for (int i = 0; i < 8; i++) {
                int j = bofs + jn[eg*8 + i];
                float hv = fmaxf(uv + g_v[j*DDIM + kc + kk], 0.f);
                es[kk*68 + eg*8 + i] = hv*sc1 + sh1;
            }
        }
        __syncthreads();
#pragma unroll
        for (int k = 0; k < 32; k++) {
            float4 a0 = *(const float4*)&es[k*68 + eg*8];
            float4 a1 = *(const float4*)&es[k*68 + eg*8 + 4];
            ulonglong2 bq0 = *(const ulonglong2*)&Ws[k*260 + dg*8];
            ulonglong2 bq1 = *(const ulonglong2*)&Ws[k*260 + dg*8 + 4];
            float av[8] = {a0.x,a0.y,a0.z,a0.w,a1.x,a1.y,a1.z,a1.w};
#pragma unroll
            for (int e = 0; e < 8; e++) {
                unsigned long long ap = pack2(av[e], av[e]);
                ffma2(acc[e][0], ap, bq0.x);
                ffma2(acc[e][1], ap, bq0.y);
                ffma2(acc[e][2], ap, bq1.x);
                ffma2(acc[e][3], ap, bq1.y);
            }
        }
        __syncthreads();
    }

    float* sb = Ws;
    float* sq = Ws + 2048;
    int node = node0 + eg;
#pragma unroll
    for (int p = 0; p < 4; p++) {
        float mx0 = -FLT_MAX, mx1 = -FLT_MAX, mn0 = FLT_MAX, mn1 = FLT_MAX;
        float s0 = 0.f, s1 = 0.f, q0 = 0.f, q1 = 0.f;
#pragma unroll
        for (int e = 0; e < 8; e++) {
            float v0, v1; unpack2(acc[e][p], v0, v1);
            v0 = fmaxf(v0, 0.f); v1 = fmaxf(v1, 0.f);
            mx0 = fmaxf(mx0, v0); mx1 = fmaxf(mx1, v1);
            mn0 = fminf(mn0, v0); mn1 = fminf(mn1, v1);
            s0 += v0; s1 += v1; q0 += v0*v0; q1 += v1*v1;
        }
        int c = dg*8 + 2*p;
        g_nmax[node*DDIM + c]     = mx0;
        g_nmax[node*DDIM + c + 1] = mx1;
        g_nmin[node*DDIM + c]     = mn0;
        g_nmin[node*DDIM + c + 1] = mn1;
        sb[eg*256 + c] = s0; sb[eg*256 + c + 1] = s1;
        sq[eg*256 + c] = q0; sq[eg*256 + c + 1] = q1;
    }
    __syncthreads();
    int d = tid;
    float ts = 0.f, tq = 0.f;
#pragma unroll
    for (int e = 0; e < 8; e++) { ts += sb[e*256 + d]; tq += sq[e*256 + d]; }
    atomicAdd(&g_stats[2*DDIM + d], ts);
    atomicAdd(&g_stats[3*DDIM + d], tq);
}

// ---------------- K5: bn2-apply on node extrema + partial max ----------------
__global__ void __launch_bounds__(256) k5_maxpart()
{
    int b = blockIdx.y;
    int ch = blockIdx.x;
    int d = threadIdx.x;
    float sc = g_mv[2*DDIM + d], sh = g_mv[3*DDIM + d];
    const float* src = (sc > 0.f) ? g_nmax : g_nmin;
    int base = b*NN + ch*256;
    float m = -FLT_MAX;
    for (int n = 0; n < 256; n++)
        m = fmaxf(m, src[(base + n)*DDIM + d]);
    g_pmax[(b*8 + ch)*DDIM + d] = m*sc + sh;
}

// ---------------- K6: final max + head MLP + l2norm ----------------
__global__ void __launch_bounds__(256) k6_final(
    const float* __restrict__ W1, const float* __restrict__ b1,
    const float* __restrict__ W2, const float* __restrict__ b2,
    float* __restrict__ out)
{
    __shared__ float sp[DDIM];
    __shared__ float sh[DDIM];
    __shared__ float red[256];
    int b = blockIdx.x, d = threadIdx.x;
    float m = -FLT_MAX;
    for (int c = 0; c < 8; c++) m = fmaxf(m, g_pmax[(b*8 + c)*DDIM + d]);
    sp[d] = m;
    __syncthreads();
    float a = b1[d];
    for (int k = 0; k < DDIM; k++) a += sp[k]*W1[k*DDIM + d];
    a = fmaxf(a, 0.f);
    sh[d] = a;
    __syncthreads();
    float o = b2[d];
    for (int k = 0; k < DDIM; k++) o += sh[k]*W2[k*DDIM + d];
    o = fmaxf(o, 0.f);
    red[d] = o*o;
    __syncthreads();
    for (int s = 128; s; s >>= 1) { if (d < s) red[d] += red[d + s]; __syncthreads(); }
    float nrm = sqrtf(red[0]);
    out[b*DDIM + d] = o / fmaxf(nrm, 1e-12f);
}

// ---------------- launch ----------------
extern "C" void kernel_launch(void* const* d_in, const int* in_sizes, int n_in,
                              void* d_out, int out_size)
{
    const int*   class_idx   = (const int*)  d_in[0];
    const float* colors      = (const float*)d_in[1];
    const float* positions   = (const float*)d_in[2];
    const float* class_table = (const float*)d_in[3];
    const float* posW1 = (const float*)d_in[4];
    const float* posb1 = (const float*)d_in[5];
    const float* posW2 = (const float*)d_in[6];
    const float* posb2 = (const float*)d_in[7];
    const float* colW1 = (const float*)d_in[8];
    const float* colb1 = (const float*)d_in[9];
    const float* colW2 = (const float*)d_in[10];
    const float* colb2 = (const float*)d_in[11];
    const float* mW    = (const float*)d_in[12];
    const float* mb    = (const float*)d_in[13];
    const float* gW1   = (const float*)d_in[14];
    const float* gb1   = (const float*)d_in[15];
    const float* gg1   = (const float*)d_in[16];
    const float* gbe1  = (const float*)d_in[17];
    const float* gW2   = (const float*)d_in[18];
    const float* gb2   = (const float*)d_in[19];
    const float* gg2   = (const float*)d_in[20];
    const float* gbe2  = (const float*)d_in[21];
    const float* lW1   = (const float*)d_in[22];
    const float* lb1   = (const float*)d_in[23];
    const float* lW2   = (const float*)d_in[24];
    const float* lb2   = (const float*)d_in[25];
    float* out = (float*)d_out;

    static int cfg_done = 0;
    if (!cfg_done) {
        cudaFuncSetAttribute(k2_mma, cudaFuncAttributeMaxDynamicSharedMemorySize, K2_SMEM_SZ);
        cfg_done = 1;
    }

    k1_features<<<NNODE/16, 256>>>(class_idx, colors, positions, class_table,
                                   posW1, posb1, posW2, posb2,
                                   colW1, colb1, colW2, colb2, mW, mb);
    k1b_split<<<NNODE*DDIM/1024, 256>>>();
    dim3 g2(NN/128, BB);
    k2_mma<<<g2, 256, K2_SMEM_SZ>>>();
    dim3 g3(4, NNODE/128);
    k3a_uv<<<g3, 256>>>(gW1, gb1);
    k3b_stats<<<NNODE/16, 256>>>();
    k_finalize<<<1, 256>>>(0, 0, gg1, gbe1);
    k4_edge2<<<NNODE/8, 256>>>(gW2, gb2);
    k_finalize<<<1, 256>>>(2*DDIM, 2*DDIM, gg2, gbe2);
    dim3 g5(8, BB);
    k5_maxpart<<<g5, 256>>>();
    k6_final<<<BB, 256>>>(lW1, lb1, lW2, lb2, out);
}

// round 7
// speedup vs baseline: 2.0688x; 1.1900x over previous
#include <cuda_runtime.h>
#include <cuda_bf16.h>
#include <math.h>
#include <float.h>
#include <stdint.h>

#define BB   8
#define NN   2048
#define DDIM 256
#define KNB  8
#define NNODE (BB*NN)         // 16384
#define NEDGE (NNODE*KNB)     // 131072
#define BN_EPS 1e-5f

// ---------------- scratch ----------------
__device__ float g_x[NNODE*DDIM];          // merged point features  [B*N, D]
__device__ __nv_bfloat16 g_xh[NNODE*DDIM]; // bf16 hi split of x
__device__ __nv_bfloat16 g_xl[NNODE*DDIM]; // bf16 lo split of x
__device__ float g_sq[NNODE];              // |x|^2 per point
__device__ int   g_nidx[NNODE*KNB];        // knn indices
__device__ float g_u[NNODE*DDIM];          // x@(W1a-W1b)+b1
__device__ float g_v[NNODE*DDIM];          // x@W1b
__device__ float g_nmax[NNODE*DDIM];       // per-node max of h2 (pre-BN2)
__device__ float g_nmin[NNODE*DDIM];       // per-node min of h2 (pre-BN2)
__device__ float g_stats[4*DDIM];          // [sum1, sqsum1, sum2, sqsum2]
__device__ float g_mv[4*DDIM];             // [scale1, shift1, scale2, shift2]
__device__ float g_pmax[BB*8*DDIM];        // partial max over nodes
// transposed bf16 hi/lo weight tables ([n][k] layout = HMMA B-fragment layout)
__device__ __nv_bfloat16 g_w1t_h[512*DDIM];  // n<256: Wu = W1a-W1b ; n>=256: Wv = W1b
__device__ __nv_bfloat16 g_w1t_l[512*DDIM];
__device__ __nv_bfloat16 g_w2t_h[DDIM*DDIM];
__device__ __nv_bfloat16 g_w2t_l[DDIM*DDIM];

// ---------------- scalar helpers ----------------
__device__ __forceinline__ unsigned long long pack2(float lo, float hi) {
    unsigned long long r;
    asm("mov.b64 %0, {%1, %2};" : "=l"(r) : "f"(lo), "f"(hi));
    return r;
}
__device__ __forceinline__ void unpack2(unsigned long long v, float& lo, float& hi) {
    asm("mov.b64 {%0, %1}, %2;" : "=f"(lo), "=f"(hi) : "l"(v));
}
__device__ __forceinline__ void ffma2(unsigned long long& d, unsigned long long a, unsigned long long b) {
    asm("fma.rn.f32x2 %0, %1, %2, %0;" : "+l"(d) : "l"(a), "l"(b));
}
__device__ __forceinline__ float wredsum(float s) {
#pragma unroll
    for (int o = 16; o; o >>= 1) s += __shfl_xor_sync(0xffffffffu, s, o);
    return s;
}
__device__ __forceinline__ bool dless(float d1, int i1, float d2, int i2) {
    return d1 < d2 || (d1 == d2 && i1 < i2);
}

// warp-level bf16 MMA: D[16x8] += A[16x16](row) * B[16x8](col = row-major [n][k]); fp32 acc
__device__ __forceinline__ void mma16816(float* c, uint32_t a0, uint32_t a1, uint32_t a2, uint32_t a3,
                                         uint32_t b0, uint32_t b1) {
    asm volatile(
        "mma.sync.aligned.m16n8k16.row.col.f32.bf16.bf16.f32 "
        "{%0,%1,%2,%3}, {%4,%5,%6,%7}, {%8,%9}, {%0,%1,%2,%3};"
        : "+f"(c[0]), "+f"(c[1]), "+f"(c[2]), "+f"(c[3])
        : "r"(a0), "r"(a1), "r"(a2), "r"(a3), "r"(b0), "r"(b1));
}
__device__ __forceinline__ void bf16split(float v, __nv_bfloat16& h, __nv_bfloat16& l) {
    h = __float2bfloat16(v);
    l = __float2bfloat16(v - __bfloat162float(h));
}

// ---------------- K1: point features + merge GEMM ----------------
__global__ void __launch_bounds__(256) k1_features(
    const int*   __restrict__ class_idx, const float* __restrict__ colors,
    const float* __restrict__ positions, const float* __restrict__ class_table,
    const float* __restrict__ posW1, const float* __restrict__ posb1,
    const float* __restrict__ posW2, const float* __restrict__ posb2,
    const float* __restrict__ colW1, const float* __restrict__ colb1,
    const float* __restrict__ colW2, const float* __restrict__ colb2,
    const float* __restrict__ mW,    const float* __restrict__ mb)
{
    __shared__ __align__(16) float fs[768*16];
    int tid = threadIdx.x, lane = tid & 31, w = tid >> 5;
    int g0 = blockIdx.x * 16;

    if (blockIdx.x == 0)
        for (int i = tid; i < 4*DDIM; i += 256) g_stats[i] = 0.f;

    for (int pp = 0; pp < 2; pp++) {
        int p = w*2 + pp;
        int g = g0 + p;
        int cls = class_idx[g];
        float v[8]; float s = 0.f;
#pragma unroll
        for (int t = 0; t < 8; t++) { v[t] = class_table[cls*DDIM + lane + 32*t]; s += v[t]*v[t]; }
        s = wredsum(s);
        float sc = 1.f / fmaxf(sqrtf(s), 1e-12f);
#pragma unroll
        for (int t = 0; t < 8; t++) fs[(lane + 32*t)*16 + p] = v[t]*sc;

        float a0 = colors[g*3+0], a1 = colors[g*3+1], a2 = colors[g*3+2];
        float h = fmaxf(colb1[lane] + a0*colW1[lane] + a1*colW1[32+lane] + a2*colW1[64+lane], 0.f);
#pragma unroll
        for (int t = 0; t < 8; t++) v[t] = colb2[lane + 32*t];
#pragma unroll 8
        for (int k = 0; k < 32; k++) {
            float hk = __shfl_sync(0xffffffffu, h, k);
#pragma unroll
            for (int t = 0; t < 8; t++) v[t] += hk * colW2[k*DDIM + lane + 32*t];
        }
        s = 0.f;
#pragma unroll
        for (int t = 0; t < 8; t++) { v[t] = fmaxf(v[t], 0.f); s += v[t]*v[t]; }
        s = wredsum(s);
        sc = 1.f / fmaxf(sqrtf(s), 1e-12f);
#pragma unroll
        for (int t = 0; t < 8; t++) fs[(256 + lane + 32*t)*16 + p] = v[t]*sc;

        a0 = positions[g*3+0]; a1 = positions[g*3+1]; a2 = positions[g*3+2];
        h = fmaxf(posb1[lane] + a0*posW1[lane] + a1*posW1[32+lane] + a2*posW1[64+lane], 0.f);
#pragma unroll
        for (int t = 0; t < 8; t++) v[t] = posb2[lane + 32*t];
#pragma unroll 8
        for (int k = 0; k < 32; k++) {
            float hk = __shfl_sync(0xffffffffu, h, k);
#pragma unroll
            for (int t = 0; t < 8; t++) v[t] += hk * posW2[k*DDIM + lane + 32*t];
        }
        s = 0.f;
#pragma unroll
        for (int t = 0; t < 8; t++) { v[t] = fmaxf(v[t], 0.f); s += v[t]*v[t]; }
        s = wredsum(s);
        sc = 1.f / fmaxf(sqrtf(s), 1e-12f);
#pragma unroll
        for (int t = 0; t < 8; t++) fs[(512 + lane + 32*t)*16 + p] = v[t]*sc;
    }
    __syncthreads();

    int d = tid;
    float bv = mb[d];
    unsigned long long acc[8];
    unsigned long long bi = pack2(bv, bv);
#pragma unroll
    for (int q = 0; q < 8; q++) acc[q] = bi;
    for (int c = 0; c < 768; c++) {
        float wv = mW[c*DDIM + d];
        unsigned long long w2 = pack2(wv, wv);
        const ulonglong2* f2 = (const ulonglong2*)&fs[c*16];
#pragma unroll
        for (int q = 0; q < 4; q++) {
            ulonglong2 u = f2[q];
            ffma2(acc[2*q],   w2, u.x);
            ffma2(acc[2*q+1], w2, u.y);
        }
    }
    __syncthreads();
    if (tid < 16) fs[tid] = 0.f;
    __syncthreads();
    float xv[16];
#pragma unroll
    for (int q = 0; q < 8; q++) {
        float v0, v1; unpack2(acc[q], v0, v1);
        v0 = fmaxf(v0, 0.f); v1 = fmaxf(v1, 0.f);
        g_x[(g0 + 2*q  )*DDIM + d] = v0;
        g_x[(g0 + 2*q+1)*DDIM + d] = v1;
        xv[2*q] = v0*v0; xv[2*q+1] = v1*v1;
    }
#pragma unroll
    for (int p = 0; p < 16; p++) {
        float s = wredsum(xv[p]);
        if (lane == 0) atomicAdd(&fs[p], s);
    }
    __syncthreads();
    if (tid < 16) g_sq[g0 + tid] = fs[tid];
}

// ---------------- K1b: split x into bf16 hi/lo ----------------
__global__ void __launch_bounds__(256) k1b_split()
{
    int i = (blockIdx.x*256 + threadIdx.x)*4;
    float4 v = *(const float4*)&g_x[i];
    __nv_bfloat16 h0, h1, h2, h3, l0, l1, l2, l3;
    bf16split(v.x, h0, l0); bf16split(v.y, h1, l1);
    bf16split(v.z, h2, l2); bf16split(v.w, h3, l3);
    __nv_bfloat162 hp0; hp0.x = h0; hp0.y = h1;
    __nv_bfloat162 hp1; hp1.x = h2; hp1.y = h3;
    __nv_bfloat162 lp0; lp0.x = l0; lp0.y = l1;
    __nv_bfloat162 lp1; lp1.x = l2; lp1.y = l3;
    *(__nv_bfloat162*)&g_xh[i]     = hp0;
    *(__nv_bfloat162*)&g_xh[i + 2] = hp1;
    *(__nv_bfloat162*)&g_xl[i]     = lp0;
    *(__nv_bfloat162*)&g_xl[i + 2] = lp1;
}

// ---------------- K_prep: transposed bf16 hi/lo weight tables ----------------
__global__ void __launch_bounds__(256) k_prep(const float* __restrict__ W1, const float* __restrict__ W2)
{
    int idx = blockIdx.x*256 + threadIdx.x;
    if (idx < 512*DDIM) {
        int n = idx >> 8, k = idx & 255;
        float val = (n < DDIM) ? (W1[k*DDIM + n] - W1[(k+DDIM)*DDIM + n])
                               : W1[(k+DDIM)*DDIM + (n - DDIM)];
        __nv_bfloat16 h, l; bf16split(val, h, l);
        g_w1t_h[idx] = h; g_w1t_l[idx] = l;
    } else {
        int i2 = idx - 512*DDIM;
        int n = i2 >> 8, k = i2 & 255;
        float val = W2[k*DDIM + n];
        __nv_bfloat16 h, l; bf16split(val, h, l);
        g_w2t_h[i2] = h; g_w2t_l[i2] = l;
    }
}

// ---------------- K2: HMMA bf16-split gram + fused top-8 ----------------
#define K2_SMEM_SZ 181248
__global__ void __launch_bounds__(256) k2_mma()
{
    extern __shared__ __align__(16) char sm[];
    float* sq_i_s = (float*)(sm + 0);
    float* sq_j_s = (float*)(sm + 512);
    float* topd   = (float*)(sm + 1024);
    int*   topi   = (int*)(sm + 5120);
    __nv_bfloat16* Ah = (__nv_bfloat16*)(sm + 9216);
    __nv_bfloat16* Al = (__nv_bfloat16*)(sm + 76800);
    __nv_bfloat16* Bh = (__nv_bfloat16*)(sm + 144384);
    __nv_bfloat16* Bl = (__nv_bfloat16*)(sm + 162816);
    float* dist = (float*)(sm + 144384);

    int tid = threadIdx.x, lane = tid & 31, w = tid >> 5;
    int b = blockIdx.y;
    int i0 = blockIdx.x * 128;
    int nb = b*NN;

    for (int s = tid; s < 1024; s += 256) { topd[s] = FLT_MAX; topi[s] = 0x7fffffff; }
    if (tid < 128) sq_i_s[tid] = g_sq[nb + i0 + tid];

    for (int s = tid; s < 128*32; s += 256) {
        int r = s >> 5, kq = (s & 31) * 8;
        int gofs = (nb + i0 + r)*DDIM + kq;
        *(uint4*)&Ah[r*264 + kq] = *(const uint4*)&g_xh[gofs];
        *(uint4*)&Al[r*264 + kq] = *(const uint4*)&g_xl[gofs];
    }
    __syncthreads();

    int m0 = w*16;
    int arow = lane >> 2;
    int kq2  = (lane & 3) * 2;

    float c[16][4];
#pragma unroll
    for (int nt = 0; nt < 16; nt++)
#pragma unroll
        for (int q = 0; q < 4; q++) c[nt][q] = 0.f;

    for (int jc = 0; jc < 16; jc++) {
        int j0 = jc * 128;
        if (tid < 128) sq_j_s[tid] = g_sq[nb + j0 + tid];

        for (int ks = 0; ks < 4; ks++) {
            for (int s = tid; s < 128*8; s += 256) {
                int r = s >> 3, kq = (s & 7) * 8;
                int gofs = (nb + j0 + r)*DDIM + ks*64 + kq;
                *(uint4*)&Bh[r*72 + kq] = *(const uint4*)&g_xh[gofs];
                *(uint4*)&Bl[r*72 + kq] = *(const uint4*)&g_xl[gofs];
            }
            __syncthreads();
#pragma unroll
            for (int k0 = 0; k0 < 64; k0 += 16) {
                int ka = ks*64 + k0 + kq2;
                uint32_t ah0 = *(const uint32_t*)&Ah[(m0+arow  )*264 + ka];
                uint32_t ah1 = *(const uint32_t*)&Ah[(m0+arow+8)*264 + ka];
                uint32_t ah2 = *(const uint32_t*)&Ah[(m0+arow  )*264 + ka + 8];
                uint32_t ah3 = *(const uint32_t*)&Ah[(m0+arow+8)*264 + ka + 8];
                uint32_t al0 = *(const uint32_t*)&Al[(m0+arow  )*264 + ka];
                uint32_t al1 = *(const uint32_t*)&Al[(m0+arow+8)*264 + ka];
                uint32_t al2 = *(const uint32_t*)&Al[(m0+arow  )*264 + ka + 8];
                uint32_t al3 = *(const uint32_t*)&Al[(m0+arow+8)*264 + ka + 8];
#pragma unroll
                for (int nt = 0; nt < 16; nt++) {
                    int br = nt*8 + arow;
                    int kb = k0 + kq2;
                    uint32_t bh0 = *(const uint32_t*)&Bh[br*72 + kb];
                    uint32_t bh1 = *(const uint32_t*)&Bh[br*72 + kb + 8];
                    uint32_t bl0 = *(const uint32_t*)&Bl[br*72 + kb];
                    uint32_t bl1 = *(const uint32_t*)&Bl[br*72 + kb + 8];
                    mma16816(c[nt], ah0, ah1, ah2, ah3, bh0, bh1);
                    mma16816(c[nt], ah0, ah1, ah2, ah3, bl0, bl1);
                    mma16816(c[nt], al0, al1, al2, al3, bh0, bh1);
                }
            }
            __syncthreads();
        }

        float sqi0 = sq_i_s[m0 + arow];
        float sqi1 = sq_i_s[m0 + arow + 8];
#pragma unroll
        for (int h = 0; h < 2; h++) {
#pragma unroll
            for (int nt8 = 0; nt8 < 8; nt8++) {
                int nt = h*8 + nt8;
                int colj = nt*8 + kq2;
                float sj0 = sq_j_s[colj], sj1 = sq_j_s[colj + 1];
                int cl = nt8*8 + kq2;
                float2 o0 = { sqi0 + sj0 - 2.f*c[nt][0], sqi0 + sj1 - 2.f*c[nt][1] };
                float2 o1 = { sqi1 + sj0 - 2.f*c[nt][2], sqi1 + sj1 - 2.f*c[nt][3] };
                *(float2*)&dist[(m0 + arow    )*68 + cl] = o0;
                *(float2*)&dist[(m0 + arow + 8)*68 + cl] = o1;
            }
            __syncthreads();
            for (int rr = 0; rr < 16; rr++) {
                int row = w*16 + rr;
#pragma unroll
                for (int ps = 0; ps < 2; ps++) {
                    float cd = dist[row*68 + ps*32 + lane];
                    int   cj = j0 + h*64 + ps*32 + lane;
                    float thr_d = topd[row*8+7]; int thr_i = topi[row*8+7];
                    bool pass = dless(cd, cj, thr_d, thr_i);
                    unsigned m = __ballot_sync(0xffffffffu, pass);
                    while (m) {
                        int src = __ffs(m) - 1; m &= m - 1;
                        float id = __shfl_sync(0xffffffffu, cd, src);
                        int   ij = __shfl_sync(0xffffffffu, cj, src);
                        if (lane == 0) {
                            if (dless(id, ij, topd[row*8+7], topi[row*8+7])) {
                                int p = 7;
                                while (p > 0 && dless(id, ij, topd[row*8+p-1], topi[row*8+p-1])) {
                                    topd[row*8+p] = topd[row*8+p-1];
                                    topi[row*8+p] = topi[row*8+p-1];
                                    p--;
                                }
                                topd[row*8+p] = id; topi[row*8+p] = ij;
                            }
                        }
                    }
                    __syncwarp();
                }
            }
            __syncthreads();
        }
#pragma unroll
        for (int nt = 0; nt < 16; nt++)
#pragma unroll
            for (int q = 0; q < 4; q++) c[nt][q] = 0.f;
    }

    for (int s = tid; s < 1024; s += 256)
        g_nidx[(nb + i0 + (s >> 3))*KNB + (s & 7)] = topi[s];
}

// ---------------- K3a: HMMA u/v GEMM ----------------
// CTA = 128 rows x 128 cols of combined [u|v] (N=512 via blockIdx.x=cg).
// smem: Ah[128][72] 0, Al 18432, Wh[128][72] 36864, Wl 55296; total 73728.
#define K3A_SMEM_SZ 73728
__global__ void __launch_bounds__(256) k3a_mma(const float* __restrict__ b1)
{
    extern __shared__ __align__(16) char sm3[];
    __nv_bfloat16* Ah = (__nv_bfloat16*)(sm3 + 0);
    __nv_bfloat16* Al = (__nv_bfloat16*)(sm3 + 18432);
    __nv_bfloat16* Wh = (__nv_bfloat16*)(sm3 + 36864);
    __nv_bfloat16* Wl = (__nv_bfloat16*)(sm3 + 55296);

    int tid = threadIdx.x, lane = tid & 31, w = tid >> 5;
    int cg = blockIdx.x;                  // 0..3 over N=512
    int r0 = blockIdx.y * 128;
    int m0 = w*16;
    int arow = lane >> 2;
    int kq2  = (lane & 3) * 2;

    float c[16][4];
#pragma unroll
    for (int nt = 0; nt < 16; nt++)
#pragma unroll
        for (int q = 0; q < 4; q++) c[nt][q] = 0.f;

    for (int ks = 0; ks < 4; ks++) {
        for (int s = tid; s < 1024; s += 256) {
            int r = s >> 3, kq = (s & 7) * 8;
            int gofs = (r0 + r)*DDIM + ks*64 + kq;
            *(uint4*)&Ah[r*72 + kq] = *(const uint4*)&g_xh[gofs];
            *(uint4*)&Al[r*72 + kq] = *(const uint4*)&g_xl[gofs];
        }
        for (int s = tid; s < 1024; s += 256) {
            int n = s >> 3, kq = (s & 7) * 8;
            int gofs = (cg*128 + n)*DDIM + ks*64 + kq;
            *(uint4*)&Wh[n*72 + kq] = *(const uint4*)&g_w1t_h[gofs];
            *(uint4*)&Wl[n*72 + kq] = *(const uint4*)&g_w1t_l[gofs];
        }
        __syncthreads();
#pragma unroll
        for (int k0 = 0; k0 < 64; k0 += 16) {
            int ka = k0 + kq2;
            uint32_t ah0 = *(const uint32_t*)&Ah[(m0+arow  )*72 + ka];
            uint32_t ah1 = *(const uint32_t*)&Ah[(m0+arow+8)*72 + ka];
            uint32_t ah2 = *(const uint32_t*)&Ah[(m0+arow  )*72 + ka + 8];
            uint32_t ah3 = *(const uint32_t*)&Ah[(m0+arow+8)*72 + ka + 8];
            uint32_t al0 = *(const uint32_t*)&Al[(m0+arow  )*72 + ka];
            uint32_t al1 = *(const uint32_t*)&Al[(m0+arow+8)*72 + ka];
            uint32_t al2 = *(const uint32_t*)&Al[(m0+arow  )*72 + ka + 8];
            uint32_t al3 = *(const uint32_t*)&Al[(m0+arow+8)*72 + ka + 8];
#pragma unroll
            for (int nt = 0; nt < 16; nt++) {
                int br = nt*8 + arow;
                uint32_t bh0 = *(const uint32_t*)&Wh[br*72 + ka];
                uint32_t bh1 = *(const uint32_t*)&Wh[br*72 + ka + 8];
                uint32_t bl0 = *(const uint32_t*)&Wl[br*72 + ka];
                uint32_t bl1 = *(const uint32_t*)&Wl[br*72 + ka + 8];
                mma16816(c[nt], ah0, ah1, ah2, ah3, bh0, bh1);
                mma16816(c[nt], ah0, ah1, ah2, ah3, bl0, bl1);
                mma16816(c[nt], al0, al1, al2, al3, bh0, bh1);
            }
        }
        __syncthreads();
    }

    bool isU = (cg < 2);
    int row0 = r0 + m0 + arow;
#pragma unroll
    for (int nt = 0; nt < 16; nt++) {
        int gcol = (cg & 1)*128 + nt*8 + kq2;
        if (isU) {
            float b0 = b1[gcol], bb1 = b1[gcol+1];
            g_u[row0*DDIM + gcol]       = c[nt][0] + b0;
            g_u[row0*DDIM + gcol + 1]   = c[nt][1] + bb1;
            g_u[(row0+8)*DDIM + gcol]   = c[nt][2] + b0;
            g_u[(row0+8)*DDIM + gcol+1] = c[nt][3] + bb1;
        } else {
            g_v[row0*DDIM + gcol]       = c[nt][0];
            g_v[row0*DDIM + gcol + 1]   = c[nt][1];
            g_v[(row0+8)*DDIM + gcol]   = c[nt][2];
            g_v[(row0+8)*DDIM + gcol+1] = c[nt][3];
        }
    }
}

// ---------------- K3b: BN1 stats over all edges ----------------
__global__ void __launch_bounds__(256) k3b_stats()
{
    __shared__ int jn[128];
    int tid = threadIdx.x;
    int node0 = blockIdx.x * 16;
    if (tid < 128) jn[tid] = g_nidx[node0*KNB + tid];
    __syncthreads();
    int d = tid;
    float s = 0.f, s2 = 0.f;
#pragma unroll 4
    for (int n = 0; n < 16; n++) {
        float un = g_u[(node0 + n)*DDIM + d];
#pragma unroll
        for (int k = 0; k < 8; k++) {
            int b = (node0 + n) >> 11;
            int j = b*NN + jn[n*8 + k];
            float hv = fmaxf(un + g_v[j*DDIM + d], 0.f);
            s += hv; s2 += hv*hv;
        }
    }
    atomicAdd(&g_stats[d], s);
    atomicAdd(&g_stats[DDIM + d], s2);
}

// ---------------- finalize BN stats ----------------
__global__ void k_finalize(int si, int mo, const float* __restrict__ gamma, const float* __restrict__ beta)
{
    int d = threadIdx.x;
    float inv = 1.f / (float)NEDGE;
    float m = g_stats[si + d] * inv;
    float v = g_stats[si + DDIM + d] * inv - m*m;
    float rstd = rsqrtf(v + BN_EPS);
    float sc = rstd * gamma[d];
    g_mv[mo + d] = sc;
    g_mv[mo + DDIM + d] = beta[d] - m*sc;
}

// ---------------- K4: HMMA edge GEMM2 (recompute h1 -> bn1 -> W2) ----------------
// CTA = 64 edges (8 nodes) x 256 cols. Warps: wm = w&3 (16-row m-tile), wn = w>>2 (128-col n-tile).
// smem: Wh[256][72] 0 (36864), Wl 36864, Eh[64][72] 73728 (9216), El 82944,
//       jn 92160 (256), mvs 92416 (2048) -> 94464. Cs[64][260] overlays Wh/Wl.
#define K4_SMEM_SZ 94464
__global__ void __launch_bounds__(256) k4_mma(const float* __restrict__ b2)
{
    extern __shared__ __align__(16) char sm4[];
    __nv_bfloat16* Wh = (__nv_bfloat16*)(sm4 + 0);
    __nv_bfloat16* Wl = (__nv_bfloat16*)(sm4 + 36864);
    __nv_bfloat16* Eh = (__nv_bfloat16*)(sm4 + 73728);
    __nv_bfloat16* El = (__nv_bfloat16*)(sm4 + 82944);
    int*   jn  = (int*)(sm4 + 92160);
    float* mvs = (float*)(sm4 + 92416);
    float* Cs  = (float*)(sm4 + 0);

    int tid = threadIdx.x, lane = tid & 31, w = tid >> 5;
    int wm = w & 3, wn = w >> 2;
    int m0 = wm*16;
    int arow = lane >> 2;
    int kq2  = (lane & 3) * 2;
    int node0 = blockIdx.x * 8;
    int bofs = (node0 >> 11) * NN;

    if (tid < 64) jn[tid] = g_nidx[node0*KNB + tid];
    for (int s = tid; s < 512; s += 256) mvs[s] = g_mv[s];
    __syncthreads();

    float c[16][4];
#pragma unroll
    for (int nt = 0; nt < 16; nt++)
#pragma unroll
        for (int q = 0; q < 4; q++) c[nt][q] = 0.f;

    int e_ = tid >> 2;                  // edge for E staging
    int kq16 = (tid & 3) * 16;
    int enode = node0 + (e_ >> 3);
    int ej = bofs + jn[e_];

    for (int ks = 0; ks < 4; ks++) {
        // stage W2T slab
        for (int s = tid; s < 2048; s += 256) {
            int n = s >> 3, kq = (s & 7) * 8;
            int gofs = n*DDIM + ks*64 + kq;
            *(uint4*)&Wh[n*72 + kq] = *(const uint4*)&g_w2t_h[gofs];
            *(uint4*)&Wl[n*72 + kq] = *(const uint4*)&g_w2t_l[gofs];
        }
        // stage E slab: es = bn1(relu(u+v)), bf16 hi/lo
#pragma unroll
        for (int t = 0; t < 4; t++) {
            int kl = ks*64 + kq16 + t*4;
            float4 uu = *(const float4*)&g_u[enode*DDIM + kl];
            float4 vv = *(const float4*)&g_v[ej*DDIM + kl];
            float h0 = fmaxf(uu.x + vv.x, 0.f)*mvs[kl+0] + mvs[DDIM+kl+0];
            float h1 = fmaxf(uu.y + vv.y, 0.f)*mvs[kl+1] + mvs[DDIM+kl+1];
            float h2 = fmaxf(uu.z + vv.z, 0.f)*mvs[kl+2] + mvs[DDIM+kl+2];
            float h3 = fmaxf(uu.w + vv.w, 0.f)*mvs[kl+3] + mvs[DDIM+kl+3];
            __nv_bfloat16 hh0,hh1,hh2,hh3,ll0,ll1,ll2,ll3;
            bf16split(h0,hh0,ll0); bf16split(h1,hh1,ll1);
            bf16split(h2,hh2,ll2); bf16split(h3,hh3,ll3);
            __nv_bfloat162 ph0; ph0.x=hh0; ph0.y=hh1;
            __nv_bfloat162 ph1; ph1.x=hh2; ph1.y=hh3;
            __nv_bfloat162 pl0; pl0.x=ll0; pl0.y=ll1;
            __nv_bfloat162 pl1; pl1.x=ll2; pl1.y=ll3;
            int eo = e_*72 + kq16 + t*4;
            *(__nv_bfloat162*)&Eh[eo]   = ph0;
            *(__nv_bfloat162*)&Eh[eo+2] = ph1;
            *(__nv_bfloat162*)&El[eo]   = pl0;
            *(__nv_bfloat162*)&El[eo+2] = pl1;
        }
        __syncthreads();
#pragma unroll
        for (int k0 = 0; k0 < 64; k0 += 16) {
            int ka = k0 + kq2;
            uint32_t ah0 = *(const uint32_t*)&Eh[(m0+arow  )*72 + ka];
            uint32_t ah1 = *(const uint32_t*)&Eh[(m0+arow+8)*72 + ka];
            uint32_t ah2 = *(const uint32_t*)&Eh[(m0+arow  )*72 + ka + 8];
            uint32_t ah3 = *(const uint32_t*)&Eh[(m0+arow+8)*72 + ka + 8];
            uint32_t al0 = *(const uint32_t*)&El[(m0+arow  )*72 + ka];
            uint32_t al1 = *(const uint32_t*)&El[(m0+arow+8)*72 + ka];
            uint32_t al2 = *(const uint32_t*)&El[(m0+arow  )*72 + ka + 8];
            uint32_t al3 = *(const uint32_t*)&El[(m0+arow+8)*72 + ka + 8];
#pragma unroll
            for (int nt = 0; nt < 16; nt++) {
                int br = wn*128 + nt*8 + arow;
                uint32_t bh0 = *(const uint32_t*)&Wh[br*72 + ka];
                uint32_t bh1 = *(const uint32_t*)&Wh[br*72 + ka + 8];
                uint32_t bl0 = *(const uint32_t*)&Wl[br*72 + ka];
                uint32_t bl1 = *(const uint32_t*)&Wl[br*72 + ka + 8];
                mma16816(c[nt], ah0, ah1, ah2, ah3, bh0, bh1);
                mma16816(c[nt], ah0, ah1, ah2, ah3, bl0, bl1);
                mma16816(c[nt], al0, al1, al2, al3, bh0, bh1);
            }
        }
        __syncthreads();
    }

    // epilogue: bias + relu -> Cs[64][260]
#pragma unroll
    for (int nt = 0; nt < 16; nt++) {
        int col = wn*128 + nt*8 + kq2;
        float b0 = b2[col], bb1 = b2[col+1];
        Cs[(m0+arow  )*260 + col]     = fmaxf(c[nt][0] + b0, 0.f);
        Cs[(m0+arow  )*260 + col + 1] = fmaxf(c[nt][1] + bb1, 0.f);
        Cs[(m0+arow+8)*260 + col]     = fmaxf(c[nt][2] + b0, 0.f);
        Cs[(m0+arow+8)*260 + col + 1] = fmaxf(c[nt][3] + bb1, 0.f);
    }
    __syncthreads();

    int d = tid;
    float ts = 0.f, tq = 0.f;
#pragma unroll
    for (int nd = 0; nd < 8; nd++) {
        float mx = -FLT_MAX, mn = FLT_MAX;
#pragma unroll
        for (int e2 = 0; e2 < 8; e2++) {
            float vv = Cs[(nd*8 + e2)*260 + d];
            mx = fmaxf(mx, vv); mn = fminf(mn, vv);
            ts += vv; tq += vv*vv;
        }
        g_nmax[(node0 + nd)*DDIM + d] = mx;
        g_nmin[(node0 + nd)*DDIM + d] = mn;
    }
    atomicAdd(&g_stats[2*DDIM + d], ts);
    atomicAdd(&g_stats[3*DDIM + d], tq);
}

// ---------------- K5: bn2-apply on node extrema + partial max ----------------
__global__ void __launch_bounds__(256) k5_maxpart()
{
    int b = blockIdx.y;
    int ch = blockIdx.x;
    int d = threadIdx.x;
    float sc = g_mv[2*DDIM + d], sh = g_mv[3*DDIM + d];
    const float* src = (sc > 0.f) ? g_nmax : g_nmin;
    int base = b*NN + ch*256;
    float m = -FLT_MAX;
    for (int n = 0; n < 256; n++)
        m = fmaxf(m, src[(base + n)*DDIM + d]);
    g_pmax[(b*8 + ch)*DDIM + d] = m*sc + sh;
}

// ---------------- K6: final max + head MLP + l2norm ----------------
__global__ void __launch_bounds__(256) k6_final(
    const float* __restrict__ W1, const float* __restrict__ b1,
    const float* __restrict__ W2, const float* __restrict__ b2,
    float* __restrict__ out)
{
    __shared__ float sp[DDIM];
    __shared__ float sh[DDIM];
    __shared__ float red[256];
    int b = blockIdx.x, d = threadIdx.x;
    float m = -FLT_MAX;
    for (int c = 0; c < 8; c++) m = fmaxf(m, g_pmax[(b*8 + c)*DDIM + d]);
    sp[d] = m;
    __syncthreads();
    float a = b1[d];
    for (int k = 0; k < DDIM; k++) a += sp[k]*W1[k*DDIM + d];
    a = fmaxf(a, 0.f);
    sh[d] = a;
    __syncthreads();
    float o = b2[d];
    for (int k = 0; k < DDIM; k++) o += sh[k]*W2[k*DDIM + d];
    o = fmaxf(o, 0.f);
    red[d] = o*o;
    __syncthreads();
    for (int s = 128; s; s >>= 1) { if (d < s) red[d] += red[d + s]; __syncthreads(); }
    float nrm = sqrtf(red[0]);
    out[b*DDIM + d] = o / fmaxf(nrm, 1e-12f);
}

// ---------------- launch ----------------
extern "C" void kernel_launch(void* const* d_in, const int* in_sizes, int n_in,
                              void* d_out, int out_size)
{
    const int*   class_idx   = (const int*)  d_in[0];
    const float* colors      = (const float*)d_in[1];
    const float* positions   = (const float*)d_in[2];
    const float* class_table = (const float*)d_in[3];
    const float* posW1 = (const float*)d_in[4];
    const float* posb1 = (const float*)d_in[5];
    const float* posW2 = (const float*)d_in[6];
    const float* posb2 = (const float*)d_in[7];
    const float* colW1 = (const float*)d_in[8];
    const float* colb1 = (const float*)d_in[9];
    const float* colW2 = (const float*)d_in[10];
    const float* colb2 = (const float*)d_in[11];
    const float* mW    = (const float*)d_in[12];
    const float* mb    = (const float*)d_in[13];
    const float* gW1   = (const float*)d_in[14];
    const float* gb1   = (const float*)d_in[15];
    const float* gg1   = (const float*)d_in[16];
    const float* gbe1  = (const float*)d_in[17];
    const float* gW2   = (const float*)d_in[18];
    const float* gb2   = (const float*)d_in[19];
    const float* gg2   = (const float*)d_in[20];
    const float* gbe2  = (const float*)d_in[21];
    const float* lW1   = (const float*)d_in[22];
    const float* lb1   = (const float*)d_in[23];
    const float* lW2   = (const float*)d_in[24];
    const float* lb2   = (const float*)d_in[25];
    float* out = (float*)d_out;

    static int cfg_done = 0;
    if (!cfg_done) {
        cudaFuncSetAttribute(k2_mma,  cudaFuncAttributeMaxDynamicSharedMemorySize, K2_SMEM_SZ);
        cudaFuncSetAttribute(k3a_mma, cudaFuncAttributeMaxDynamicSharedMemorySize, K3A_SMEM_SZ);
        cudaFuncSetAttribute(k4_mma,  cudaFuncAttributeMaxDynamicSharedMemorySize, K4_SMEM_SZ);
        cfg_done = 1;
    }

    k_prep<<<768, 256>>>(gW1, gW2);
    k1_features<<<NNODE/16, 256>>>(class_idx, colors, positions, class_table,
                                   posW1, posb1, posW2, posb2,
                                   colW1, colb1, colW2, colb2, mW, mb);
    k1b_split<<<NNODE*DDIM/1024, 256>>>();
    dim3 g2(NN/128, BB);
    k2_mma<<<g2, 256, K2_SMEM_SZ>>>();
    dim3 g3(4, NNODE/128);
    k3a_mma<<<g3, 256, K3A_SMEM_SZ>>>(gb1);
    k3b_stats<<<NNODE/16, 256>>>();
    k_finalize<<<1, 256>>>(0, 0, gg1, gbe1);
    k4_mma<<<NNODE/8, 256, K4_SMEM_SZ>>>(gb2);
    k_finalize<<<1, 256>>>(2*DDIM, 2*DDIM, gg2, gbe2);
    dim3 g5(8, BB);
    k5_maxpart<<<g5, 256>>>();
    k6_final<<<BB, 256>>>(lW1, lb1, lW2, lb2, out);
}

// round 9
// speedup vs baseline: 2.4961x; 1.2065x over previous
#include <cuda_runtime.h>
#include <cuda_bf16.h>
#include <math.h>
#include <float.h>
#include <stdint.h>

#define BB   8
#define NN   2048
#define DDIM 256
#define KNB  8
#define NNODE (BB*NN)         // 16384
#define NEDGE (NNODE*KNB)     // 131072
#define BN_EPS 1e-5f

// ---------------- scratch ----------------
__device__ float g_x[NNODE*DDIM];          // merged point features  [B*N, D]
__device__ __nv_bfloat16 g_xh[NNODE*DDIM]; // bf16 hi split of x
__device__ __nv_bfloat16 g_xl[NNODE*DDIM]; // bf16 lo split of x
__device__ float g_sq[NNODE];              // |x|^2 per point
__device__ int   g_nidx[NNODE*KNB];        // knn indices
__device__ float g_u[NNODE*DDIM];          // x@(W1a-W1b)+b1
__device__ float g_v[NNODE*DDIM];          // x@W1b
__device__ float g_nmax[NNODE*DDIM];       // per-node max of h2 (pre-BN2)
__device__ float g_nmin[NNODE*DDIM];       // per-node min of h2 (pre-BN2)
__device__ float g_stats[4*DDIM];          // [sum1, sqsum1, sum2, sqsum2]
__device__ float g_mv[4*DDIM];             // [scale1, shift1, scale2, shift2]
__device__ float g_pmax[BB*8*DDIM];        // partial max over nodes
// transposed bf16 hi/lo weight tables ([n][k] layout = HMMA B-fragment layout)
__device__ __nv_bfloat16 g_w1t_h[512*DDIM];  // n<256: Wu = W1a-W1b ; n>=256: Wv = W1b
__device__ __nv_bfloat16 g_w1t_l[512*DDIM];
__device__ __nv_bfloat16 g_w2t_h[DDIM*DDIM];
__device__ __nv_bfloat16 g_w2t_l[DDIM*DDIM];

// ---------------- scalar helpers ----------------
__device__ __forceinline__ unsigned long long pack2(float lo, float hi) {
    unsigned long long r;
    asm("mov.b64 %0, {%1, %2};" : "=l"(r) : "f"(lo), "f"(hi));
    return r;
}
__device__ __forceinline__ void unpack2(unsigned long long v, float& lo, float& hi) {
    asm("mov.b64 {%0, %1}, %2;" : "=f"(lo), "=f"(hi) : "l"(v));
}
__device__ __forceinline__ void ffma2(unsigned long long& d, unsigned long long a, unsigned long long b) {
    asm("fma.rn.f32x2 %0, %1, %2, %0;" : "+l"(d) : "l"(a), "l"(b));
}
__device__ __forceinline__ float wredsum(float s) {
#pragma unroll
    for (int o = 16; o; o >>= 1) s += __shfl_xor_sync(0xffffffffu, s, o);
    return s;
}
__device__ __forceinline__ bool dless(float d1, int i1, float d2, int i2) {
    return d1 < d2 || (d1 == d2 && i1 < i2);
}

// warp-level bf16 MMA: D[16x8] += A[16x16](row) * B[16x8](col = row-major [n][k]); fp32 acc
__device__ __forceinline__ void mma16816(float* c, uint32_t a0, uint32_t a1, uint32_t a2, uint32_t a3,
                                         uint32_t b0, uint32_t b1) {
    asm volatile(
        "mma.sync.aligned.m16n8k16.row.col.f32.bf16.bf16.f32 "
        "{%0,%1,%2,%3}, {%4,%5,%6,%7}, {%8,%9}, {%0,%1,%2,%3};"
        : "+f"(c[0]), "+f"(c[1]), "+f"(c[2]), "+f"(c[3])
        : "r"(a0), "r"(a1), "r"(a2), "r"(a3), "r"(b0), "r"(b1));
}
__device__ __forceinline__ void bf16split(float v, __nv_bfloat16& h, __nv_bfloat16& l) {
    h = __float2bfloat16(v);
    l = __float2bfloat16(v - __bfloat162float(h));
}

// ---------------- K1: point features + merge GEMM ----------------
__global__ void __launch_bounds__(256) k1_features(
    const int*   __restrict__ class_idx, const float* __restrict__ colors,
    const float* __restrict__ positions, const float* __restrict__ class_table,
    const float* __restrict__ posW1, const float* __restrict__ posb1,
    const float* __restrict__ posW2, const float* __restrict__ posb2,
    const float* __restrict__ colW1, const float* __restrict__ colb1,
    const float* __restrict__ colW2, const float* __restrict__ colb2,
    const float* __restrict__ mW,    const float* __restrict__ mb)
{
    __shared__ __align__(16) float fs[768*16];
    int tid = threadIdx.x, lane = tid & 31, w = tid >> 5;
    int g0 = blockIdx.x * 16;

    if (blockIdx.x == 0)
        for (int i = tid; i < 4*DDIM; i += 256) g_stats[i] = 0.f;

    for (int pp = 0; pp < 2; pp++) {
        int p = w*2 + pp;
        int g = g0 + p;
        int cls = class_idx[g];
        float v[8]; float s = 0.f;
#pragma unroll
        for (int t = 0; t < 8; t++) { v[t] = class_table[cls*DDIM + lane + 32*t]; s += v[t]*v[t]; }
        s = wredsum(s);
        float sc = 1.f / fmaxf(sqrtf(s), 1e-12f);
#pragma unroll
        for (int t = 0; t < 8; t++) fs[(lane + 32*t)*16 + p] = v[t]*sc;

        float a0 = colors[g*3+0], a1 = colors[g*3+1], a2 = colors[g*3+2];
        float h = fmaxf(colb1[lane] + a0*colW1[lane] + a1*colW1[32+lane] + a2*colW1[64+lane], 0.f);
#pragma unroll
        for (int t = 0; t < 8; t++) v[t] = colb2[lane + 32*t];
#pragma unroll 8
        for (int k = 0; k < 32; k++) {
            float hk = __shfl_sync(0xffffffffu, h, k);
#pragma unroll
            for (int t = 0; t < 8; t++) v[t] += hk * colW2[k*DDIM + lane + 32*t];
        }
        s = 0.f;
#pragma unroll
        for (int t = 0; t < 8; t++) { v[t] = fmaxf(v[t], 0.f); s += v[t]*v[t]; }
        s = wredsum(s);
        sc = 1.f / fmaxf(sqrtf(s), 1e-12f);
#pragma unroll
        for (int t = 0; t < 8; t++) fs[(256 + lane + 32*t)*16 + p] = v[t]*sc;

        a0 = positions[g*3+0]; a1 = positions[g*3+1]; a2 = positions[g*3+2];
        h = fmaxf(posb1[lane] + a0*posW1[lane] + a1*posW1[32+lane] + a2*posW1[64+lane], 0.f);
#pragma unroll
        for (int t = 0; t < 8; t++) v[t] = posb2[lane + 32*t];
#pragma unroll 8
        for (int k = 0; k < 32; k++) {
            float hk = __shfl_sync(0xffffffffu, h, k);
#pragma unroll
            for (int t = 0; t < 8; t++) v[t] += hk * posW2[k*DDIM + lane + 32*t];
        }
        s = 0.f;
#pragma unroll
        for (int t = 0; t < 8; t++) { v[t] = fmaxf(v[t], 0.f); s += v[t]*v[t]; }
        s = wredsum(s);
        sc = 1.f / fmaxf(sqrtf(s), 1e-12f);
#pragma unroll
        for (int t = 0; t < 8; t++) fs[(512 + lane + 32*t)*16 + p] = v[t]*sc;
    }
    __syncthreads();

    int d = tid;
    float bv = mb[d];
    unsigned long long acc[8];
    unsigned long long bi = pack2(bv, bv);
#pragma unroll
    for (int q = 0; q < 8; q++) acc[q] = bi;
    for (int c = 0; c < 768; c++) {
        float wv = mW[c*DDIM + d];
        unsigned long long w2 = pack2(wv, wv);
        const ulonglong2* f2 = (const ulonglong2*)&fs[c*16];
#pragma unroll
        for (int q = 0; q < 4; q++) {
            ulonglong2 u = f2[q];
            ffma2(acc[2*q],   w2, u.x);
            ffma2(acc[2*q+1], w2, u.y);
        }
    }
    __syncthreads();
    if (tid < 16) fs[tid] = 0.f;
    __syncthreads();
    float xv[16];
#pragma unroll
    for (int q = 0; q < 8; q++) {
        float v0, v1; unpack2(acc[q], v0, v1);
        v0 = fmaxf(v0, 0.f); v1 = fmaxf(v1, 0.f);
        g_x[(g0 + 2*q  )*DDIM + d] = v0;
        g_x[(g0 + 2*q+1)*DDIM + d] = v1;
        xv[2*q] = v0*v0; xv[2*q+1] = v1*v1;
    }
#pragma unroll
    for (int p = 0; p < 16; p++) {
        float s = wredsum(xv[p]);
        if (lane == 0) atomicAdd(&fs[p], s);
    }
    __syncthreads();
    if (tid < 16) g_sq[g0 + tid] = fs[tid];
}

// ---------------- K1b: split x into bf16 hi/lo ----------------
__global__ void __launch_bounds__(256) k1b_split()
{
    int i = (blockIdx.x*256 + threadIdx.x)*4;
    float4 v = *(const float4*)&g_x[i];
    __nv_bfloat16 h0, h1, h2, h3, l0, l1, l2, l3;
    bf16split(v.x, h0, l0); bf16split(v.y, h1, l1);
    bf16split(v.z, h2, l2); bf16split(v.w, h3, l3);
    __nv_bfloat162 hp0; hp0.x = h0; hp0.y = h1;
    __nv_bfloat162 hp1; hp1.x = h2; hp1.y = h3;
    __nv_bfloat162 lp0; lp0.x = l0; lp0.y = l1;
    __nv_bfloat162 lp1; lp1.x = l2; lp1.y = l3;
    *(__nv_bfloat162*)&g_xh[i]     = hp0;
    *(__nv_bfloat162*)&g_xh[i + 2] = hp1;
    *(__nv_bfloat162*)&g_xl[i]     = lp0;
    *(__nv_bfloat162*)&g_xl[i + 2] = lp1;
}

// ---------------- K_prep: transposed bf16 hi/lo weight tables ----------------
__global__ void __launch_bounds__(256) k_prep(const float* __restrict__ W1, const float* __restrict__ W2)
{
    int idx = blockIdx.x*256 + threadIdx.x;
    if (idx < 512*DDIM) {
        int n = idx >> 8, k = idx & 255;
        float val = (n < DDIM) ? (W1[k*DDIM + n] - W1[(k+DDIM)*DDIM + n])
                               : W1[(k+DDIM)*DDIM + (n - DDIM)];
        __nv_bfloat16 h, l; bf16split(val, h, l);
        g_w1t_h[idx] = h; g_w1t_l[idx] = l;
    } else {
        int i2 = idx - 512*DDIM;
        int n = i2 >> 8, k = i2 & 255;
        float val = W2[k*DDIM + n];
        __nv_bfloat16 h, l; bf16split(val, h, l);
        g_w2t_h[i2] = h; g_w2t_l[i2] = l;
    }
}

// ---------------- K2: HMMA bf16-split gram + fused top-8 (64-row CTAs, 2 CTAs/SM) ----------------
// CTA = 64 i-rows of one batch (grid 32 x 8 = 256 CTAs).
// Warp split: wm = w&3 -> 16-row m-tile; wn = w>>2 -> 64-col n-half of the 128-j chunk.
// smem bytes:
//   [0)      sq_i   64 f         = 256
//   [256)    sq_j   128 f        = 512
//   [768)    topd   512 f        = 2048
//   [2816)   topi   512 i        = 2048
//   [4864)   Ah     64*264 bf16  = 33792
//   [38656)  Al     64*264 bf16  = 33792
//   [72448)  Bh     128*72 bf16  = 18432   (overlaid by dist[64][132] f = 33792)
//   [90880)  Bl     128*72 bf16  = 18432
//   total 109312  -> 2 CTAs/SM
#define K2_SMEM_SZ 109312

__global__ void __launch_bounds__(256) k2_mma()
{
    extern __shared__ __align__(16) char sm[];
    float* sq_i_s = (float*)(sm + 0);
    float* sq_j_s = (float*)(sm + 256);
    float* topd   = (float*)(sm + 768);
    int*   topi   = (int*)(sm + 2816);
    __nv_bfloat16* Ah = (__nv_bfloat16*)(sm + 4864);
    __nv_bfloat16* Al = (__nv_bfloat16*)(sm + 38656);
    __nv_bfloat16* Bh = (__nv_bfloat16*)(sm + 72448);
    __nv_bfloat16* Bl = (__nv_bfloat16*)(sm + 90880);
    float* dist = (float*)(sm + 72448);    // overlays Bh/Bl after K accumulation

    int tid = threadIdx.x, lane = tid & 31, w = tid >> 5;
    int b = blockIdx.y;
    int i0 = blockIdx.x * 64;
    int nb = b*NN;

    for (int s = tid; s < 512; s += 256) { topd[s] = FLT_MAX; topi[s] = 0x7fffffff; }
    if (tid < 64) sq_i_s[tid] = g_sq[nb + i0 + tid];

    // stage A hi/lo: [64][264] row-major halves
    for (int s = tid; s < 64*32; s += 256) {
        int r = s >> 5, kq = (s & 31) * 8;
        int gofs = (nb + i0 + r)*DDIM + kq;
        *(uint4*)&Ah[r*264 + kq] = *(const uint4*)&g_xh[gofs];
        *(uint4*)&Al[r*264 + kq] = *(const uint4*)&g_xl[gofs];
    }
    __syncthreads();

    int wm = w & 3, wn = w >> 2;
    int m0 = wm*16;
    int arow = lane >> 2;            // 0..7
    int kq2  = (lane & 3) * 2;       // 0,2,4,6

    float c[8][4];
#pragma unroll
    for (int nt = 0; nt < 8; nt++)
#pragma unroll
        for (int q = 0; q < 4; q++) c[nt][q] = 0.f;

    for (int jc = 0; jc < 16; jc++) {
        int j0 = jc * 128;
        if (tid < 128) sq_j_s[tid] = g_sq[nb + j0 + tid];

        for (int ks = 0; ks < 4; ks++) {
            // stage B slab: rows j0..j0+127, feats ks*64..ks*64+63
            for (int s = tid; s < 128*8; s += 256) {
                int r = s >> 3, kq = (s & 7) * 8;
                int gofs = (nb + j0 + r)*DDIM + ks*64 + kq;
                *(uint4*)&Bh[r*72 + kq] = *(const uint4*)&g_xh[gofs];
                *(uint4*)&Bl[r*72 + kq] = *(const uint4*)&g_xl[gofs];
            }
            __syncthreads();
#pragma unroll
            for (int k0 = 0; k0 < 64; k0 += 16) {
                int ka = ks*64 + k0 + kq2;
                uint32_t ah0 = *(const uint32_t*)&Ah[(m0+arow  )*264 + ka];
                uint32_t ah1 = *(const uint32_t*)&Ah[(m0+arow+8)*264 + ka];
                uint32_t ah2 = *(const uint32_t*)&Ah[(m0+arow  )*264 + ka + 8];
                uint32_t ah3 = *(const uint32_t*)&Ah[(m0+arow+8)*264 + ka + 8];
                uint32_t al0 = *(const uint32_t*)&Al[(m0+arow  )*264 + ka];
                uint32_t al1 = *(const uint32_t*)&Al[(m0+arow+8)*264 + ka];
                uint32_t al2 = *(const uint32_t*)&Al[(m0+arow  )*264 + ka + 8];
                uint32_t al3 = *(const uint32_t*)&Al[(m0+arow+8)*264 + ka + 8];
                int kb = k0 + kq2;
#pragma unroll
                for (int nt = 0; nt < 8; nt++) {
                    int br = wn*64 + nt*8 + arow;
                    uint32_t bh0 = *(const uint32_t*)&Bh[br*72 + kb];
                    uint32_t bh1 = *(const uint32_t*)&Bh[br*72 + kb + 8];
                    uint32_t bl0 = *(const uint32_t*)&Bl[br*72 + kb];
                    uint32_t bl1 = *(const uint32_t*)&Bl[br*72 + kb + 8];
                    mma16816(c[nt], ah0, ah1, ah2, ah3, bh0, bh1);
                    mma16816(c[nt], ah0, ah1, ah2, ah3, bl0, bl1);
                    mma16816(c[nt], al0, al1, al2, al3, bh0, bh1);
                }
            }
            __syncthreads();
        }

        // epilogue: dist[64][132] for full 128-col chunk, then top-8
        float sqi0 = sq_i_s[m0 + arow];
        float sqi1 = sq_i_s[m0 + arow + 8];
#pragma unroll
        for (int nt = 0; nt < 8; nt++) {
            int colj = wn*64 + nt*8 + kq2;
            float sj0 = sq_j_s[colj], sj1 = sq_j_s[colj + 1];
            float2 o0 = { sqi0 + sj0 - 2.f*c[nt][0], sqi0 + sj1 - 2.f*c[nt][1] };
            float2 o1 = { sqi1 + sj0 - 2.f*c[nt][2], sqi1 + sj1 - 2.f*c[nt][3] };
            *(float2*)&dist[(m0 + arow    )*132 + colj] = o0;
            *(float2*)&dist[(m0 + arow + 8)*132 + colj] = o1;
        }
        __syncthreads();
        for (int rr = 0; rr < 8; rr++) {
            int row = w*8 + rr;
#pragma unroll
            for (int ps = 0; ps < 4; ps++) {
                float cd = dist[row*132 + ps*32 + lane];
                int   cj = j0 + ps*32 + lane;
                float thr_d = topd[row*8+7]; int thr_i = topi[row*8+7];
                bool pass = dless(cd, cj, thr_d, thr_i);
                unsigned m = __ballot_sync(0xffffffffu, pass);
                while (m) {
                    int src = __ffs(m) - 1; m &= m - 1;
                    float id = __shfl_sync(0xffffffffu, cd, src);
                    int   ij = __shfl_sync(0xffffffffu, cj, src);
                    if (lane == 0) {
                        if (dless(id, ij, topd[row*8+7], topi[row*8+7])) {
                            int p = 7;
                            while (p > 0 && dless(id, ij, topd[row*8+p-1], topi[row*8+p-1])) {
                                topd[row*8+p] = topd[row*8+p-1];
                                topi[row*8+p] = topi[row*8+p-1];
                                p--;
                            }
                            topd[row*8+p] = id; topi[row*8+p] = ij;
                        }
                    }
                }
                __syncwarp();
            }
        }
        __syncthreads();
#pragma unroll
        for (int nt = 0; nt < 8; nt++)
#pragma unroll
            for (int q = 0; q < 4; q++) c[nt][q] = 0.f;
    }

    for (int s = tid; s < 512; s += 256)
        g_nidx[(nb + i0 + (s >> 3))*KNB + (s & 7)] = topi[s];
}

// ---------------- K3a: HMMA u/v GEMM ----------------
#define K3A_SMEM_SZ 73728
__global__ void __launch_bounds__(256) k3a_mma(const float* __restrict__ b1)
{
    extern __shared__ __align__(16) char sm3[];
    __nv_bfloat16* Ah = (__nv_bfloat16*)(sm3 + 0);
    __nv_bfloat16* Al = (__nv_bfloat16*)(sm3 + 18432);
    __nv_bfloat16* Wh = (__nv_bfloat16*)(sm3 + 36864);
    __nv_bfloat16* Wl = (__nv_bfloat16*)(sm3 + 55296);

    int tid = threadIdx.x, lane = tid & 31, w = tid >> 5;
    int cg = blockIdx.x;                  // 0..3 over N=512
    int r0 = blockIdx.y * 128;
    int m0 = w*16;
    int arow = lane >> 2;
    int kq2  = (lane & 3) * 2;

    float c[16][4];
#pragma unroll
    for (int nt = 0; nt < 16; nt++)
#pragma unroll
        for (int q = 0; q < 4; q++) c[nt][q] = 0.f;

    for (int ks = 0; ks < 4; ks++) {
        for (int s = tid; s < 1024; s += 256) {
            int r = s >> 3, kq = (s & 7) * 8;
            int gofs = (r0 + r)*DDIM + ks*64 + kq;
            *(uint4*)&Ah[r*72 + kq] = *(const uint4*)&g_xh[gofs];
            *(uint4*)&Al[r*72 + kq] = *(const uint4*)&g_xl[gofs];
        }
        for (int s = tid; s < 1024; s += 256) {
            int n = s >> 3, kq = (s & 7) * 8;
            int gofs = (cg*128 + n)*DDIM + ks*64 + kq;
            *(uint4*)&Wh[n*72 + kq] = *(const uint4*)&g_w1t_h[gofs];
            *(uint4*)&Wl[n*72 + kq] = *(const uint4*)&g_w1t_l[gofs];
        }
        __syncthreads();
#pragma unroll
        for (int k0 = 0; k0 < 64; k0 += 16) {
            int ka = k0 + kq2;
            uint32_t ah0 = *(const uint32_t*)&Ah[(m0+arow  )*72 + ka];
            uint32_t ah1 = *(const uint32_t*)&Ah[(m0+arow+8)*72 + ka];
            uint32_t ah2 = *(const uint32_t*)&Ah[(m0+arow  )*72 + ka + 8];
            uint32_t ah3 = *(const uint32_t*)&Ah[(m0+arow+8)*72 + ka + 8];
            uint32_t al0 = *(const uint32_t*)&Al[(m0+arow  )*72 + ka];
            uint32_t al1 = *(const uint32_t*)&Al[(m0+arow+8)*72 + ka];
            uint32_t al2 = *(const uint32_t*)&Al[(m0+arow  )*72 + ka + 8];
            uint32_t al3 = *(const uint32_t*)&Al[(m0+arow+8)*72 + ka + 8];
#pragma unroll
            for (int nt = 0; nt < 16; nt++) {
                int br = nt*8 + arow;
                uint32_t bh0 = *(const uint32_t*)&Wh[br*72 + ka];
                uint32_t bh1 = *(const uint32_t*)&Wh[br*72 + ka + 8];
                uint32_t bl0 = *(const uint32_t*)&Wl[br*72 + ka];
                uint32_t bl1 = *(const uint32_t*)&Wl[br*72 + ka + 8];
                mma16816(c[nt], ah0, ah1, ah2, ah3, bh0, bh1);
                mma16816(c[nt], ah0, ah1, ah2, ah3, bl0, bl1);
                mma16816(c[nt], al0, al1, al2, al3, bh0, bh1);
            }
        }
        __syncthreads();
    }

    bool isU = (cg < 2);
    int row0 = r0 + m0 + arow;
#pragma unroll
    for (int nt = 0; nt < 16; nt++) {
        int gcol = (cg & 1)*128 + nt*8 + kq2;
        if (isU) {
            float b0 = b1[gcol], bb1 = b1[gcol+1];
            g_u[row0*DDIM + gcol]       = c[nt][0] + b0;
            g_u[row0*DDIM + gcol + 1]   = c[nt][1] + bb1;
            g_u[(row0+8)*DDIM + gcol]   = c[nt][2] + b0;
            g_u[(row0+8)*DDIM + gcol+1] = c[nt][3] + bb1;
        } else {
            g_v[row0*DDIM + gcol]       = c[nt][0];
            g_v[row0*DDIM + gcol + 1]   = c[nt][1];
            g_v[(row0+8)*DDIM + gcol]   = c[nt][2];
            g_v[(row0+8)*DDIM + gcol+1] = c[nt][3];
        }
    }
}

// ---------------- K3b: BN1 stats over all edges ----------------
__global__ void __launch_bounds__(256) k3b_stats()
{
    __shared__ int jn[128];
    int tid = threadIdx.x;
    int node0 = blockIdx.x * 16;
    if (tid < 128) jn[tid] = g_nidx[node0*KNB + tid];
    __syncthreads();
    int d = tid;
    float s = 0.f, s2 = 0.f;
#pragma unroll 4
    for (int n = 0; n < 16; n++) {
        float un = g_u[(node0 + n)*DDIM + d];
#pragma unroll
        for (int k = 0; k < 8; k++) {
            int b = (node0 + n) >> 11;
            int j = b*NN + jn[n*8 + k];
            float hv = fmaxf(un + g_v[j*DDIM + d], 0.f);
            s += hv; s2 += hv*hv;
        }
    }
    atomicAdd(&g_stats[d], s);
    atomicAdd(&g_stats[DDIM + d], s2);
}

// ---------------- finalize BN stats ----------------
__global__ void k_finalize(int si, int mo, const float* __restrict__ gamma, const float* __restrict__ beta)
{
    int d = threadIdx.x;
    float inv = 1.f / (float)NEDGE;
    float m = g_stats[si + d] * inv;
    float v = g_stats[si + DDIM + d] * inv - m*m;
    float rstd = rsqrtf(v + BN_EPS);
    float sc = rstd * gamma[d];
    g_mv[mo + d] = sc;
    g_mv[mo + DDIM + d] = beta[d] - m*sc;
}

// ---------------- K4: HMMA edge GEMM2 (recompute h1 -> bn1 -> W2) ----------------
#define K4_SMEM_SZ 94464
__global__ void __launch_bounds__(256) k4_mma(const float* __restrict__ b2)
{
    extern __shared__ __align__(16) char sm4[];
    __nv_bfloat16* Wh = (__nv_bfloat16*)(sm4 + 0);
    __nv_bfloat16* Wl = (__nv_bfloat16*)(sm4 + 36864);
    __nv_bfloat16* Eh = (__nv_bfloat16*)(sm4 + 73728);
    __nv_bfloat16* El = (__nv_bfloat16*)(sm4 + 82944);
    int*   jn  = (int*)(sm4 + 92160);
    float* mvs = (float*)(sm4 + 92416);
    float* Cs  = (float*)(sm4 + 0);

    int tid = threadIdx.x, lane = tid & 31, w = tid >> 5;
    int wm = w & 3, wn = w >> 2;
    int m0 = wm*16;
    int arow = lane >> 2;
    int kq2  = (lane & 3) * 2;
    int node0 = blockIdx.x * 8;
    int bofs = (node0 >> 11) * NN;

    if (tid < 64) jn[tid] = g_nidx[node0*KNB + tid];
    for (int s = tid; s < 512; s += 256) mvs[s] = g_mv[s];
    __syncthreads();

    float c[16][4];
#pragma unroll
    for (int nt = 0; nt < 16; nt++)
#pragma unroll
        for (int q = 0; q < 4; q++) c[nt][q] = 0.f;

    int e_ = tid >> 2;
    int kq16 = (tid & 3) * 16;
    int enode = node0 + (e_ >> 3);
    int ej = bofs + jn[e_];

    for (int ks = 0; ks < 4; ks++) {
        for (int s = tid; s < 2048; s += 256) {
            int n = s >> 3, kq = (s & 7) * 8;
            int gofs = n*DDIM + ks*64 + kq;
            *(uint4*)&Wh[n*72 + kq] = *(const uint4*)&g_w2t_h[gofs];
            *(uint4*)&Wl[n*72 + kq] = *(const uint4*)&g_w2t_l[gofs];
        }
#pragma unroll
        for (int t = 0; t < 4; t++) {
            int kl = ks*64 + kq16 + t*4;
            float4 uu = *(const float4*)&g_u[enode*DDIM + kl];
            float4 vv = *(const float4*)&g_v[ej*DDIM + kl];
            float h0 = fmaxf(uu.x + vv.x, 0.f)*mvs[kl+0] + mvs[DDIM+kl+0];
            float h1 = fmaxf(uu.y + vv.y, 0.f)*mvs[kl+1] + mvs[DDIM+kl+1];
            float h2 = fmaxf(uu.z + vv.z, 0.f)*mvs[kl+2] + mvs[DDIM+kl+2];
            float h3 = fmaxf(uu.w + vv.w, 0.f)*mvs[kl+3] + mvs[DDIM+kl+3];
            __nv_bfloat16 hh0,hh1,hh2,hh3,ll0,ll1,ll2,ll3;
            bf16split(h0,hh0,ll0); bf16split(h1,hh1,ll1);
            bf16split(h2,hh2,ll2); bf16split(h3,hh3,ll3);
            __nv_bfloat162 ph0; ph0.x=hh0; ph0.y=hh1;
            __nv_bfloat162 ph1; ph1.x=hh2; ph1.y=hh3;
            __nv_bfloat162 pl0; pl0.x=ll0; pl0.y=ll1;
            __nv_bfloat162 pl1; pl1.x=ll2; pl1.y=ll3;
            int eo = e_*72 + kq16 + t*4;
            *(__nv_bfloat162*)&Eh[eo]   = ph0;
            *(__nv_bfloat162*)&Eh[eo+2] = ph1;
            *(__nv_bfloat162*)&El[eo]   = pl0;
            *(__nv_bfloat162*)&El[eo+2] = pl1;
        }
        __syncthreads();
#pragma unroll
        for (int k0 = 0; k0 < 64; k0 += 16) {
            int ka = k0 + kq2;
            uint32_t ah0 = *(const uint32_t*)&Eh[(m0+arow  )*72 + ka];
            uint32_t ah1 = *(const uint32_t*)&Eh[(m0+arow+8)*72 + ka];
            uint32_t ah2 = *(const uint32_t*)&Eh[(m0+arow  )*72 + ka + 8];
            uint32_t ah3 = *(const uint32_t*)&Eh[(m0+arow+8)*72 + ka + 8];
            uint32_t al0 = *(const uint32_t*)&El[(m0+arow  )*72 + ka];
            uint32_t al1 = *(const uint32_t*)&El[(m0+arow+8)*72 + ka];
            uint32_t al2 = *(const uint32_t*)&El[(m0+arow  )*72 + ka + 8];
            uint32_t al3 = *(const uint32_t*)&El[(m0+arow+8)*72 + ka + 8];
#pragma unroll
            for (int nt = 0; nt < 16; nt++) {
                int br = wn*128 + nt*8 + arow;
                uint32_t bh0 = *(const uint32_t*)&Wh[br*72 + ka];
                uint32_t bh1 = *(const uint32_t*)&Wh[br*72 + ka + 8];
                uint32_t bl0 = *(const uint32_t*)&Wl[br*72 + ka];
                uint32_t bl1 = *(const uint32_t*)&Wl[br*72 + ka + 8];
                mma16816(c[nt], ah0, ah1, ah2, ah3, bh0, bh1);
                mma16816(c[nt], ah0, ah1, ah2, ah3, bl0, bl1);
                mma16816(c[nt], al0, al1, al2, al3, bh0, bh1);
            }
        }
        __syncthreads();
    }

#pragma unroll
    for (int nt = 0; nt < 16; nt++) {
        int col = wn*128 + nt*8 + kq2;
        float b0 = b2[col], bb1 = b2[col+1];
        Cs[(m0+arow  )*260 + col]     = fmaxf(c[nt][0] + b0, 0.f);
        Cs[(m0+arow  )*260 + col + 1] = fmaxf(c[nt][1] + bb1, 0.f);
        Cs[(m0+arow+8)*260 + col]     = fmaxf(c[nt][2] + b0, 0.f);
        Cs[(m0+arow+8)*260 + col + 1] = fmaxf(c[nt][3] + bb1, 0.f);
    }
    __syncthreads();

    int d = tid;
    float ts = 0.f, tq = 0.f;
#pragma unroll
    for (int nd = 0; nd < 8; nd++) {
        float mx = -FLT_MAX, mn = FLT_MAX;
#pragma unroll
        for (int e2 = 0; e2 < 8; e2++) {
            float vv = Cs[(nd*8 + e2)*260 + d];
            mx = fmaxf(mx, vv); mn = fminf(mn, vv);
            ts += vv; tq += vv*vv;
        }
        g_nmax[(node0 + nd)*DDIM + d] = mx;
        g_nmin[(node0 + nd)*DDIM + d] = mn;
    }
    atomicAdd(&g_stats[2*DDIM + d], ts);
    atomicAdd(&g_stats[3*DDIM + d], tq);
}

// ---------------- K5: bn2-apply on node extrema + partial max ----------------
__global__ void __launch_bounds__(256) k5_maxpart()
{
    int b = blockIdx.y;
    int ch = blockIdx.x;
    int d = threadIdx.x;
    float sc = g_mv[2*DDIM + d], sh = g_mv[3*DDIM + d];
    const float* src = (sc > 0.f) ? g_nmax : g_nmin;
    int base = b*NN + ch*256;
    float m = -FLT_MAX;
    for (int n = 0; n < 256; n++)
        m = fmaxf(m, src[(base + n)*DDIM + d]);
    g_pmax[(b*8 + ch)*DDIM + d] = m*sc + sh;
}

// ---------------- K6: final max + head MLP + l2norm ----------------
__global__ void __launch_bounds__(256) k6_final(
    const float* __restrict__ W1, const float* __restrict__ b1,
    const float* __restrict__ W2, const float* __restrict__ b2,
    float* __restrict__ out)
{
    __shared__ float sp[DDIM];
    __shared__ float sh[DDIM];
    __shared__ float red[256];
    int b = blockIdx.x, d = threadIdx.x;
    float m = -FLT_MAX;
    for (int c = 0; c < 8; c++) m = fmaxf(m, g_pmax[(b*8 + c)*DDIM + d]);
    sp[d] = m;
    __syncthreads();
    float a = b1[d];
    for (int k = 0; k < DDIM; k++) a += sp[k]*W1[k*DDIM + d];
    a = fmaxf(a, 0.f);
    sh[d] = a;
    __syncthreads();
    float o = b2[d];
    for (int k = 0; k < DDIM; k++) o += sh[k]*W2[k*DDIM + d];
    o = fmaxf(o, 0.f);
    red[d] = o*o;
    __syncthreads();
    for (int s = 128; s; s >>= 1) { if (d < s) red[d] += red[d + s]; __syncthreads(); }
    float nrm = sqrtf(red[0]);
    out[b*DDIM + d] = o / fmaxf(nrm, 1e-12f);
}

// ---------------- launch ----------------
extern "C" void kernel_launch(void* const* d_in, const int* in_sizes, int n_in,
                              void* d_out, int out_size)
{
    const int*   class_idx   = (const int*)  d_in[0];
    const float* colors      = (const float*)d_in[1];
    const float* positions   = (const float*)d_in[2];
    const float* class_table = (const float*)d_in[3];
    const float* posW1 = (const float*)d_in[4];
    const float* posb1 = (const float*)d_in[5];
    const float* posW2 = (const float*)d_in[6];
    const float* posb2 = (const float*)d_in[7];
    const float* colW1 = (const float*)d_in[8];
    const float* colb1 = (const float*)d_in[9];
    const float* colW2 = (const float*)d_in[10];
    const float* colb2 = (const float*)d_in[11];
    const float* mW    = (const float*)d_in[12];
    const float* mb    = (const float*)d_in[13];
    const float* gW1   = (const float*)d_in[14];
    const float* gb1   = (const float*)d_in[15];
    const float* gg1   = (const float*)d_in[16];
    const float* gbe1  = (const float*)d_in[17];
    const float* gW2   = (const float*)d_in[18];
    const float* gb2   = (const float*)d_in[19];
    const float* gg2   = (const float*)d_in[20];
    const float* gbe2  = (const float*)d_in[21];
    const float* lW1   = (const float*)d_in[22];
    const float* lb1   = (const float*)d_in[23];
    const float* lW2   = (const float*)d_in[24];
    const float* lb2   = (const float*)d_in[25];
    float* out = (float*)d_out;

    static int cfg_done = 0;
    if (!cfg_done) {
        cudaFuncSetAttribute(k2_mma,  cudaFuncAttributeMaxDynamicSharedMemorySize, K2_SMEM_SZ);
        cudaFuncSetAttribute(k3a_mma, cudaFuncAttributeMaxDynamicSharedMemorySize, K3A_SMEM_SZ);
        cudaFuncSetAttribute(k4_mma,  cudaFuncAttributeMaxDynamicSharedMemorySize, K4_SMEM_SZ);
        cfg_done = 1;
    }

    k_prep<<<768, 256>>>(gW1, gW2);
    k1_features<<<NNODE/16, 256>>>(class_idx, colors, positions, class_table,
                                   posW1, posb1, posW2, posb2,
                                   colW1, colb1, colW2, colb2, mW, mb);
    k1b_split<<<NNODE*DDIM/1024, 256>>>();
    dim3 g2(NN/64, BB);
    k2_mma<<<g2, 256, K2_SMEM_SZ>>>();
    dim3 g3(4, NNODE/128);
    k3a_mma<<<g3, 256, K3A_SMEM_SZ>>>(gb1);
    k3b_stats<<<NNODE/16, 256>>>();
    k_finalize<<<1, 256>>>(0, 0, gg1, gbe1);
    k4_mma<<<NNODE/8, 256, K4_SMEM_SZ>>>(gb2);
    k_finalize<<<1, 256>>>(2*DDIM, 2*DDIM, gg2, gbe2);
    dim3 g5(8, BB);
    k5_maxpart<<<g5, 256>>>();
    k6_final<<<BB, 256>>>(lW1, lb1, lW2, lb2, out);
}